// round 4
// baseline (speedup 1.0000x reference)
#include <cuda_runtime.h>
#include <cstdint>

#define NBATCH 16
#define NA 128
#define HD 256
#define EF 30

#define SELU_SCALE 1.0507009873554805f
#define SELU_SCALE_ALPHA 1.7580993408473766f

// intermediate h1 (16*128*256 fp32 = 2 MB)
__device__ float g_h1[NBATCH * NA * HD];

__device__ __forceinline__ uint32_t f2tf(float x) {
    uint32_t u; asm("cvt.rna.tf32.f32 %0, %1;" : "=r"(u) : "f"(x)); return u;
}
__device__ __forceinline__ float selu_f(float d) {
    return d > 0.f ? SELU_SCALE * d : SELU_SCALE_ALPHA * (__expf(d) - 1.f);
}
__device__ __forceinline__ void mma_tf32(float c[4],
                                         uint32_t a0, uint32_t a1, uint32_t a2, uint32_t a3,
                                         uint32_t b0, uint32_t b1) {
    asm volatile(
        "mma.sync.aligned.m16n8k8.row.col.f32.tf32.tf32.f32 "
        "{%0,%1,%2,%3}, {%4,%5,%6,%7}, {%8,%9}, {%0,%1,%2,%3};"
        : "+f"(c[0]), "+f"(c[1]), "+f"(c[2]), "+f"(c[3])
        : "r"(a0), "r"(a1), "r"(a2), "r"(a3), "r"(b0), "r"(b1));
}

// -------------------------------------------------------------------------
// Kernel 1: CTA = (b, i-tile of 16). grid = 16*8 = 128.
// GEMM rows r = jj*16 + i_l (jj-major!) so each m16 tile = 16 i's at one j:
// the j-reduction is a serial per-lane accumulation across m-tiles.
// Per j-tile of 16: stage A = e rows (256 x 32 tf32, stride 36, conflict-
// free frag reads), stage h[b, j-tile, :] (16 x 256) in smem reused by all
// i. em[b, i-tile, :] staged once (stride 132, bank-spread).
// Wf fragments preloaded from gmem to regs (tiny, L1-resident).
// acc[nb][4] per lane = h1 for (i_l = r, r+8) x (f = f0+nb*8+2c, +1).
// -------------------------------------------------------------------------
#define AS 36
#define EMS 132
#define K1_SMEM ((256 * AS + 16 * HD + 16 * EMS) * 4)

__global__ __launch_bounds__(256) void efconv_k1(
    const float* __restrict__ hbuf, const float* __restrict__ e,
    const float* __restrict__ edge_mask, const float* __restrict__ Wf,
    const float* __restrict__ bf)
{
    extern __shared__ uint32_t sm1[];
    uint32_t* a_s  = sm1;                               // [256][36] tf32
    float*    h_s  = (float*)(sm1 + 256 * AS);          // [16][256]
    float*    em_s = (float*)(sm1 + 256 * AS + 16 * HD);// [16][132]

    const int tid = threadIdx.x;
    const int w = tid >> 5, l = tid & 31;
    const int r = l >> 2, c = l & 3;
    const int b = blockIdx.x >> 3, it = blockIdx.x & 7;
    const int i0 = it * 16;
    const int f0 = w * 32;

    // ---- stage em[b, i0:i0+16, :] once ----
    #pragma unroll
    for (int q = 0; q < 8; q++) {
        int idx = tid + q * 256;
        int i_l = idx >> 7, j = idx & 127;
        em_s[i_l * EMS + j] = edge_mask[((b * NA) + i0 + i_l) * NA + j];
    }

    // ---- preload Wf fragments (k-pad to 32 with zeros) ----
    uint32_t B[4][4][2];
    #pragma unroll
    for (int ks = 0; ks < 4; ks++)
        #pragma unroll
        for (int nb = 0; nb < 4; nb++) {
            int fr = f0 + nb * 8 + r;
            int k0 = ks * 8 + c, k1 = ks * 8 + c + 4;
            B[ks][nb][0] = f2tf(Wf[fr * EF + k0]);                  // k0 <= 27
            B[ks][nb][1] = (k1 < EF) ? f2tf(Wf[fr * EF + k1]) : 0u;
        }
    float2 bfv[4];
    #pragma unroll
    for (int nb = 0; nb < 4; nb++)
        bfv[nb] = *(const float2*)(bf + f0 + nb * 8 + 2 * c);

    const float* eb = e + (size_t)(b * NA + i0) * (NA * EF);
    const float* hb = hbuf + (size_t)b * NA * HD;

    float acc[4][4] = {};

    #pragma unroll 1
    for (int jt = 0; jt < 8; jt++) {
        // ---- stage A: thread = row (jj = tid>>4, i_l = tid&15) ----
        {
            int i_l = tid & 15, jj = tid >> 4;
            const float2* src = (const float2*)(eb + ((size_t)i_l * NA + jt * 16 + jj) * EF);
            uint32_t* dst = a_s + tid * AS;
            #pragma unroll
            for (int p = 0; p < 15; p++) {
                float2 v = src[p];
                dst[2 * p] = f2tf(v.x);
                dst[2 * p + 1] = f2tf(v.y);
            }
            dst[30] = 0u; dst[31] = 0u;
        }
        // ---- stage h[b, jt*16 : +16, :] ----
        #pragma unroll
        for (int q = 0; q < 4; q++) {
            int idx = tid + q * 256;
            int jj = idx >> 6, fq = idx & 63;
            *(float4*)(h_s + jj * HD + fq * 4) =
                *(const float4*)(hb + (size_t)(jt * 16 + jj) * HD + fq * 4);
        }
        __syncthreads();

        #pragma unroll 4
        for (int t = 0; t < 16; t++) {
            float C[4][4] = {};
            #pragma unroll
            for (int ks = 0; ks < 4; ks++) {
                const uint32_t* ar = a_s + (t * 16 + r) * AS + ks * 8 + c;
                uint32_t a0 = ar[0], a2 = ar[4];
                uint32_t a1 = ar[8 * AS], a3 = ar[8 * AS + 4];
                #pragma unroll
                for (int nb = 0; nb < 4; nb++)
                    mma_tf32(C[nb], a0, a1, a2, a3, B[ks][nb][0], B[ks][nb][1]);
            }
            const int jc = jt * 16 + t;
            const float em0 = em_s[r * EMS + jc];
            const float em1 = em_s[(r + 8) * EMS + jc];
            #pragma unroll
            for (int nb = 0; nb < 4; nb++) {
                float2 hv = *(const float2*)(h_s + t * HD + f0 + nb * 8 + 2 * c);
                float s0 = selu_f(C[nb][0] + bfv[nb].x) * em0;
                float s1 = selu_f(C[nb][1] + bfv[nb].y) * em0;
                float s2 = selu_f(C[nb][2] + bfv[nb].x) * em1;
                float s3 = selu_f(C[nb][3] + bfv[nb].y) * em1;
                acc[nb][0] = fmaf(s0, hv.x, acc[nb][0]);
                acc[nb][1] = fmaf(s1, hv.y, acc[nb][1]);
                acc[nb][2] = fmaf(s2, hv.x, acc[nb][2]);
                acc[nb][3] = fmaf(s3, hv.y, acc[nb][3]);
            }
        }
        __syncthreads();
    }

    // ---- write h1: lane owns (i_l = r, r+8) x 4 f-pairs ----
    #pragma unroll
    for (int nb = 0; nb < 4; nb++) {
        int f = f0 + nb * 8 + 2 * c;
        *(float2*)(g_h1 + (size_t)(b * NA + i0 + r) * HD + f) =
            make_float2(acc[nb][0], acc[nb][1]);
        *(float2*)(g_h1 + (size_t)(b * NA + i0 + r + 8) * HD + f) =
            make_float2(acc[nb][2], acc[nb][3]);
    }
}

// -------------------------------------------------------------------------
// Kernel 2: out = selu([h|h1] @ Ww^T + bw) * nm + h
// GEMM M=2048, K=512, N=256. Grid 256 = 64 rb x 4 fb; CTA = 32 rows x 64 f.
// 8 warps: rt = w&1 (16-row half), fh = w>>1 (16-f quarter).
// K in 8 chunks of 64; z stride 68, w stride 73 (transposed, 2-way max).
// smem 27.4 KB static -> 4+ CTAs/SM for latency hiding.
// -------------------------------------------------------------------------
#define ZS 68
#define WS2 73

__global__ __launch_bounds__(256) void efconv_k2(
    const float* __restrict__ hbuf, const float* __restrict__ node_mask,
    const float* __restrict__ Ww, const float* __restrict__ bw,
    float* __restrict__ out)
{
    __shared__ uint32_t z_s[32 * ZS];   // [32][68] tf32
    __shared__ uint32_t w_s[64 * WS2];  // [64][73] tf32 (k-major)

    const int tid = threadIdx.x;
    const int w = tid >> 5, l = tid & 31;
    const int r = l >> 2, c = l & 3;
    const int rb = blockIdx.x >> 2, fb = blockIdx.x & 3;
    const int row0 = rb * 32;
    const int rt = w & 1, fh = w >> 1;

    float C[2][4] = {};

    #pragma unroll 1
    for (int kc = 0; kc < 8; kc++) {
        const float* zsrc = (kc < 4) ? hbuf : g_h1;
        const int cb = (kc & 3) * 64;
        // stage z: 32 rows x 64 k (2 float4 / thread, coalesced)
        #pragma unroll
        for (int q = 0; q < 2; q++) {
            int idx = tid + q * 256;
            int rr = idx >> 4, kq = idx & 15;
            float4 v = *(const float4*)(zsrc + (size_t)(row0 + rr) * HD + cb + kq * 4);
            uint32_t* d = z_s + rr * ZS + kq * 4;
            d[0] = f2tf(v.x); d[1] = f2tf(v.y); d[2] = f2tf(v.z); d[3] = f2tf(v.w);
        }
        // stage Ww chunk transposed: [k][f'] (coalesced LDG, 2-way STS)
        #pragma unroll
        for (int q = 0; q < 4; q++) {
            int idx = tid + q * 256;
            int ff = idx >> 4, kq = idx & 15;
            float4 v = *(const float4*)(Ww + (size_t)(fb * 64 + ff) * (2 * HD) + kc * 64 + kq * 4);
            w_s[(kq * 4 + 0) * WS2 + ff] = f2tf(v.x);
            w_s[(kq * 4 + 1) * WS2 + ff] = f2tf(v.y);
            w_s[(kq * 4 + 2) * WS2 + ff] = f2tf(v.z);
            w_s[(kq * 4 + 3) * WS2 + ff] = f2tf(v.w);
        }
        __syncthreads();

        #pragma unroll
        for (int ks = 0; ks < 8; ks++) {
            const uint32_t* ar = z_s + (rt * 16 + r) * ZS + ks * 8 + c;
            uint32_t a0 = ar[0], a2 = ar[4];
            uint32_t a1 = ar[8 * ZS], a3 = ar[8 * ZS + 4];
            #pragma unroll
            for (int nb = 0; nb < 2; nb++) {
                uint32_t b0 = w_s[(ks * 8 + c) * WS2     + fh * 16 + nb * 8 + r];
                uint32_t b1 = w_s[(ks * 8 + c + 4) * WS2 + fh * 16 + nb * 8 + r];
                mma_tf32(C[nb], a0, a1, a2, a3, b0, b1);
            }
        }
        __syncthreads();
    }

    // ---- epilogue: selu(D + bw) * nm + h ----
    const int rg0 = row0 + rt * 16 + r, rg1 = rg0 + 8;
    const float nm0 = node_mask[rg0], nm1 = node_mask[rg1];
    #pragma unroll
    for (int nb = 0; nb < 2; nb++) {
        int f = fb * 64 + fh * 16 + nb * 8 + 2 * c;
        float2 bv = *(const float2*)(bw + f);
        float2 h0 = *(const float2*)(hbuf + (size_t)rg0 * HD + f);
        float2 h1 = *(const float2*)(hbuf + (size_t)rg1 * HD + f);
        float2 o0, o1;
        o0.x = selu_f(C[nb][0] + bv.x) * nm0 + h0.x;
        o0.y = selu_f(C[nb][1] + bv.y) * nm0 + h0.y;
        o1.x = selu_f(C[nb][2] + bv.x) * nm1 + h1.x;
        o1.y = selu_f(C[nb][3] + bv.y) * nm1 + h1.y;
        *(float2*)(out + (size_t)rg0 * HD + f) = o0;
        *(float2*)(out + (size_t)rg1 * HD + f) = o1;
    }
}

extern "C" void kernel_launch(void* const* d_in, const int* in_sizes, int n_in,
                              void* d_out, int out_size)
{
    const float* h   = (const float*)d_in[0];   // (16,128,256)
    const float* e   = (const float*)d_in[1];   // (16,128,128,30)
    const float* nm  = (const float*)d_in[2];   // (16,128,1)
    const float* em  = (const float*)d_in[3];   // (16,128,128,1)
    const float* Wf  = (const float*)d_in[4];   // (256,30)
    const float* bf  = (const float*)d_in[5];   // (256,)
    const float* Ww  = (const float*)d_in[6];   // (256,512)
    const float* bw  = (const float*)d_in[7];   // (256,)
    float* out = (float*)d_out;                  // (16,128,256)

    cudaFuncSetAttribute(efconv_k1, cudaFuncAttributeMaxDynamicSharedMemorySize, K1_SMEM);

    efconv_k1<<<NBATCH * 8, 256, K1_SMEM>>>(h, e, em, Wf, bf);
    efconv_k2<<<256, 256>>>(h, nm, Ww, bw, out);
}

// round 5
// speedup vs baseline: 1.7132x; 1.7132x over previous
#include <cuda_runtime.h>
#include <cstdint>

#define NBATCH 16
#define NA 128
#define HD 256
#define EF 30

#define SELU_SCALE 1.0507009873554805f
#define SELU_SA    1.7580993408473766f   // scale * alpha

// intermediate h1 (16*128*256 fp32 = 2 MB)
__device__ float g_h1[NBATCH * NA * HD];

__device__ __forceinline__ uint32_t f2tf(float x) {
    uint32_t u; asm("cvt.rna.tf32.f32 %0, %1;" : "=r"(u) : "f"(x)); return u;
}
// selu = SCALE*max(d,0) + min(SA*exp(d)-SA, 0)   (3 fma-pipe + 2 alu + 1 mufu)
__device__ __forceinline__ float selu_f(float d) {
    float e = __expf(d);
    return fmaf(SELU_SCALE, fmaxf(d, 0.f), fminf(fmaf(SELU_SA, e, -SELU_SA), 0.f));
}
__device__ __forceinline__ void mma_tf32(float c[4],
                                         uint32_t a0, uint32_t a1, uint32_t a2, uint32_t a3,
                                         uint32_t b0, uint32_t b1) {
    asm volatile(
        "mma.sync.aligned.m16n8k8.row.col.f32.tf32.tf32.f32 "
        "{%0,%1,%2,%3}, {%4,%5,%6,%7}, {%8,%9}, {%0,%1,%2,%3};"
        : "+f"(c[0]), "+f"(c[1]), "+f"(c[2]), "+f"(c[3])
        : "r"(a0), "r"(a1), "r"(a2), "r"(a3), "r"(b0), "r"(b1));
}

// -------------------------------------------------------------------------
// Kernel 1: CTA = (b, i-tile of 8, f-half of 128). grid = 16*16*2 = 512.
// Per j-stage of 16: A rows rr = jj*8 + i_l (j-major): every m16 tile t is
// (j = 2t: i 0..7 | j = 2t+1: i 0..7)  ->  j-reduction is a serial per-lane
// accumulation (lane owns output (i = r, f-pair)). h[b, j-tile, f-half]
// staged in smem (reused by all 8 i); em[b, i-tile, :] staged once.
// Wf fragments from gmem (L1-resident, 30 KB). Bias folded into C init.
// A staging coalesced: for fixed i_l the 16 j-rows are 1920 contiguous
// floats in e. a_s stride 36 -> conflict-free frag reads (bank = 4r + c).
// -------------------------------------------------------------------------
#define AS 36
#define EMS 132

__global__ __launch_bounds__(256) void efconv_k1(
    const float* __restrict__ hbuf, const float* __restrict__ e,
    const float* __restrict__ edge_mask, const float* __restrict__ Wf,
    const float* __restrict__ bf)
{
    __shared__ uint32_t a_s[128 * AS];   // 18 KB
    __shared__ float    h_s[16 * 128];   //  8 KB
    __shared__ float    em_s[8 * EMS];   //  4.2 KB

    const int tid = threadIdx.x;
    const int w = tid >> 5, l = tid & 31;
    const int r = l >> 2, c = l & 3;
    const int bid = blockIdx.x;
    const int fh = bid & 1, it = (bid >> 1) & 15, b = bid >> 5;
    const int i0 = it * 8;
    const int fbase = fh * 128;

    // ---- preload Wf fragments (k padded to 32) + bias pairs ----
    uint32_t B[4][2][2];
    float2 bfv[2];
    #pragma unroll
    for (int nb = 0; nb < 2; nb++) {
        const int fr = fbase + w * 16 + nb * 8 + r;
        #pragma unroll
        for (int ks = 0; ks < 4; ks++) {
            int k0 = ks * 8 + c, k1 = k0 + 4;
            B[ks][nb][0] = f2tf(Wf[fr * EF + k0]);
            B[ks][nb][1] = (k1 < EF) ? f2tf(Wf[fr * EF + k1]) : 0u;
        }
        bfv[nb] = *(const float2*)(bf + fbase + w * 16 + nb * 8 + 2 * c);
    }

    // ---- stage em[b, i0:i0+8, :] once ----
    #pragma unroll
    for (int q = 0; q < 4; q++) {
        int idx = tid + q * 256;
        int i_l = idx >> 7, j = idx & 127;
        em_s[i_l * EMS + j] = edge_mask[((b * NA) + i0 + i_l) * NA + j];
    }
    // ---- zero-pad k = 30,31 of all 128 A rows (written once) ----
    if (tid < 128) { a_s[tid * AS + 30] = 0u; a_s[tid * AS + 31] = 0u; }

    float acc[2][2] = {};

    #pragma unroll 1
    for (int jt = 0; jt < 8; jt++) {
        // ---- stage A: (i_l, jj, p), contiguous over (jj, p) per i_l ----
        #pragma unroll
        for (int q = 0; q < 8; q++) {
            int idx = tid + q * 256;
            if (idx < 1920) {
                int i_l = idx / 240;
                int rem = idx - i_l * 240;
                int jj = rem / 15;
                int p  = rem - jj * 15;
                const float2 v = *(const float2*)(
                    e + ((size_t)((b * NA + i0 + i_l) * NA) + jt * 16 + jj) * EF + 2 * p);
                uint32_t* d = a_s + (jj * 8 + i_l) * AS + 2 * p;
                d[0] = f2tf(v.x); d[1] = f2tf(v.y);
            }
        }
        // ---- stage h[b, jt*16 : +16, f-half] ----
        #pragma unroll
        for (int q = 0; q < 2; q++) {
            int idx = tid + q * 256;
            int jj = idx >> 5, fq = idx & 31;
            *(float4*)(h_s + jj * 128 + fq * 4) =
                *(const float4*)(hbuf + (size_t)(b * NA + jt * 16 + jj) * HD + fbase + fq * 4);
        }
        __syncthreads();

        #pragma unroll
        for (int t = 0; t < 8; t++) {
            float C[2][4];
            #pragma unroll
            for (int nb = 0; nb < 2; nb++) {
                C[nb][0] = bfv[nb].x; C[nb][1] = bfv[nb].y;
                C[nb][2] = bfv[nb].x; C[nb][3] = bfv[nb].y;
            }
            #pragma unroll
            for (int ks = 0; ks < 4; ks++) {
                const uint32_t* ar = a_s + (t * 16 + r) * AS + ks * 8 + c;
                uint32_t a0 = ar[0], a2 = ar[4];
                uint32_t a1 = ar[8 * AS], a3 = ar[8 * AS + 4];
                mma_tf32(C[0], a0, a1, a2, a3, B[ks][0][0], B[ks][0][1]);
                mma_tf32(C[1], a0, a1, a2, a3, B[ks][1][0], B[ks][1][1]);
            }
            // em for (i = r, j = jt*16 + 2t, +1) — contiguous pair
            const float2 emv = *(const float2*)(em_s + r * EMS + jt * 16 + 2 * t);
            #pragma unroll
            for (int nb = 0; nb < 2; nb++) {
                const int fl = w * 16 + nb * 8 + 2 * c;
                float2 h0 = *(const float2*)(h_s + (2 * t) * 128 + fl);
                float2 h1 = *(const float2*)(h_s + (2 * t + 1) * 128 + fl);
                float s0 = selu_f(C[nb][0]) * emv.x;
                float s1 = selu_f(C[nb][1]) * emv.x;
                float s2 = selu_f(C[nb][2]) * emv.y;
                float s3 = selu_f(C[nb][3]) * emv.y;
                acc[nb][0] = fmaf(s0, h0.x, acc[nb][0]);
                acc[nb][1] = fmaf(s1, h0.y, acc[nb][1]);
                acc[nb][0] = fmaf(s2, h1.x, acc[nb][0]);
                acc[nb][1] = fmaf(s3, h1.y, acc[nb][1]);
            }
        }
        __syncthreads();
    }

    // ---- write h1: lane owns (i = i0 + r) x 2 f-pairs ----
    #pragma unroll
    for (int nb = 0; nb < 2; nb++) {
        const int f = fbase + w * 16 + nb * 8 + 2 * c;
        *(float2*)(g_h1 + (size_t)(b * NA + i0 + r) * HD + f) =
            make_float2(acc[nb][0], acc[nb][1]);
    }
}

// -------------------------------------------------------------------------
// Kernel 2: out = selu([h|h1] @ Ww^T + bw) * nm + h
// GEMM M=2048, K=512, N=256. Grid 512 = 64 rb x 8 fb; CTA = 32 rows x 32 f.
// 8 warps: rt = w&1 (16-row half), fh = w>>1 (8-f slice).
// K in 8 chunks of 64; z stride 68 (bank 4r+c), w stride 40 (bank 8c+r).
// smem ~19 KB, ~40 regs -> 3-4 CTAs/SM.
// -------------------------------------------------------------------------
#define ZS 68
#define WS2 40

__global__ __launch_bounds__(256) void efconv_k2(
    const float* __restrict__ hbuf, const float* __restrict__ node_mask,
    const float* __restrict__ Ww, const float* __restrict__ bw,
    float* __restrict__ out)
{
    __shared__ uint32_t z_s[32 * ZS];   // [32 rows][68]
    __shared__ uint32_t w_s[64 * WS2];  // [64 k][40]  (k-major, 32 f)

    const int tid = threadIdx.x;
    const int w = tid >> 5, l = tid & 31;
    const int r = l >> 2, c = l & 3;
    const int rb = blockIdx.x >> 3, fb = blockIdx.x & 7;
    const int row0 = rb * 32;
    const int rt = w & 1, fh = w >> 1;

    float C[4] = {};
    {   // fold bias into C init: c0,c1 = f-pair at row r; c2,c3 at row r+8
        float2 bv = *(const float2*)(bw + fb * 32 + fh * 8 + 2 * c);
        C[0] = bv.x; C[1] = bv.y; C[2] = bv.x; C[3] = bv.y;
    }

    #pragma unroll 1
    for (int kc = 0; kc < 8; kc++) {
        const float* zsrc = (kc < 4) ? hbuf : g_h1;
        const int cb = (kc & 3) * 64;
        // stage z: 32 rows x 64 k (2 float4 / thread, coalesced)
        #pragma unroll
        for (int q = 0; q < 2; q++) {
            int idx = tid + q * 256;
            int rr = idx >> 4, kq = idx & 15;
            float4 v = *(const float4*)(zsrc + (size_t)(row0 + rr) * HD + cb + kq * 4);
            uint32_t* d = z_s + rr * ZS + kq * 4;
            d[0] = f2tf(v.x); d[1] = f2tf(v.y); d[2] = f2tf(v.z); d[3] = f2tf(v.w);
        }
        // stage Ww chunk transposed: 32 f x 64 k -> w_s[k][f]
        #pragma unroll
        for (int q = 0; q < 2; q++) {
            int idx = tid + q * 256;
            int ff = idx >> 4, kq = idx & 15;
            float4 v = *(const float4*)(Ww + (size_t)(fb * 32 + ff) * (2 * HD) + kc * 64 + kq * 4);
            w_s[(kq * 4 + 0) * WS2 + ff] = f2tf(v.x);
            w_s[(kq * 4 + 1) * WS2 + ff] = f2tf(v.y);
            w_s[(kq * 4 + 2) * WS2 + ff] = f2tf(v.z);
            w_s[(kq * 4 + 3) * WS2 + ff] = f2tf(v.w);
        }
        __syncthreads();

        #pragma unroll
        for (int ks = 0; ks < 8; ks++) {
            const uint32_t* ar = z_s + (rt * 16 + r) * ZS + ks * 8 + c;
            uint32_t a0 = ar[0], a2 = ar[4];
            uint32_t a1 = ar[8 * ZS], a3 = ar[8 * ZS + 4];
            uint32_t b0 = w_s[(ks * 8 + c) * WS2     + fh * 8 + r];
            uint32_t b1 = w_s[(ks * 8 + c + 4) * WS2 + fh * 8 + r];
            mma_tf32(C, a0, a1, a2, a3, b0, b1);
        }
        __syncthreads();
    }

    // ---- epilogue: selu(D) * nm + h  (bias already in C) ----
    const int rg0 = row0 + rt * 16 + r, rg1 = rg0 + 8;
    const float nm0 = node_mask[rg0], nm1 = node_mask[rg1];
    const int f = fb * 32 + fh * 8 + 2 * c;
    float2 h0 = *(const float2*)(hbuf + (size_t)rg0 * HD + f);
    float2 h1 = *(const float2*)(hbuf + (size_t)rg1 * HD + f);
    float2 o0, o1;
    o0.x = selu_f(C[0]) * nm0 + h0.x;
    o0.y = selu_f(C[1]) * nm0 + h0.y;
    o1.x = selu_f(C[2]) * nm1 + h1.x;
    o1.y = selu_f(C[3]) * nm1 + h1.y;
    *(float2*)(out + (size_t)rg0 * HD + f) = o0;
    *(float2*)(out + (size_t)rg1 * HD + f) = o1;
}

extern "C" void kernel_launch(void* const* d_in, const int* in_sizes, int n_in,
                              void* d_out, int out_size)
{
    const float* h   = (const float*)d_in[0];   // (16,128,256)
    const float* e   = (const float*)d_in[1];   // (16,128,128,30)
    const float* nm  = (const float*)d_in[2];   // (16,128,1)
    const float* em  = (const float*)d_in[3];   // (16,128,128,1)
    const float* Wf  = (const float*)d_in[4];   // (256,30)
    const float* bf  = (const float*)d_in[5];   // (256,)
    const float* Ww  = (const float*)d_in[6];   // (256,512)
    const float* bw  = (const float*)d_in[7];   // (256,)
    float* out = (float*)d_out;                  // (16,128,256)

    efconv_k1<<<512, 256>>>(h, e, em, Wf, bf);
    efconv_k2<<<512, 256>>>(h, nm, Ww, bw, out);
}

// round 6
// speedup vs baseline: 2.1021x; 1.2270x over previous
#include <cuda_runtime.h>
#include <cstdint>

#define NBATCH 16
#define NA 128
#define HD 256
#define EF 30

#define SELU_SCALE 1.0507009873554805f
#define SELU_SA    1.7580993408473766f   // scale * alpha

// intermediate h1 (16*128*256 fp32 = 2 MB)
__device__ float g_h1[NBATCH * NA * HD];

__device__ __forceinline__ uint32_t f2tf(float x) {
    uint32_t u; asm("cvt.rna.tf32.f32 %0, %1;" : "=r"(u) : "f"(x)); return u;
}
// selu = SCALE*max(d,0) + min(SA*exp(d)-SA, 0)
__device__ __forceinline__ float selu_f(float d) {
    float e = __expf(d);
    return fmaf(SELU_SCALE, fmaxf(d, 0.f), fminf(fmaf(SELU_SA, e, -SELU_SA), 0.f));
}
__device__ __forceinline__ void mma_tf32(float c[4],
                                         uint32_t a0, uint32_t a1, uint32_t a2, uint32_t a3,
                                         uint32_t b0, uint32_t b1) {
    asm volatile(
        "mma.sync.aligned.m16n8k8.row.col.f32.tf32.tf32.f32 "
        "{%0,%1,%2,%3}, {%4,%5,%6,%7}, {%8,%9}, {%0,%1,%2,%3};"
        : "+f"(c[0]), "+f"(c[1]), "+f"(c[2]), "+f"(c[3])
        : "r"(a0), "r"(a1), "r"(a2), "r"(a3), "r"(b0), "r"(b1));
}

// -------------------------------------------------------------------------
// Kernel 1: CTA = (b, i-tile of 8), full 256 f. grid = 16*16 = 256.
// A rows rr = jj*8 + i_l (j-major): m16 tile t = (j=2t: i 0..7 | j=2t+1:
// i 0..7) -> j-reduction is serial per-lane accumulation.
// A stored in FRAGMENT ORDER: a_frag[(t*4+ks)*32 + lane][0..3] = the 4 mma
// regs -> one LDS.128 per (t,ks) per lane (conflict-free, 128B/phase).
// h stored j-parity-interleaved: hpair[t*512 + f*2 + (j&1)] -> one
// broadcast LDS.128 per (t,nb). Warp owns 32 f (nb=4): 1 frag LDS.128
// feeds 4 mmas. Wf frags + biases in registers. em in smem (stride 132).
// -------------------------------------------------------------------------
#define EMS 132

__global__ __launch_bounds__(256, 2) void efconv_k1(
    const float* __restrict__ hbuf, const float* __restrict__ e,
    const float* __restrict__ edge_mask, const float* __restrict__ Wf,
    const float* __restrict__ bf)
{
    __shared__ uint32_t a_frag[32 * 32 * 4];   // 16 KB (t,ks)x(lane)x(reg)
    __shared__ float    hpair[8 * 512];        // 16 KB [t][f][par]
    __shared__ float    em_s[8 * EMS];         //  4.2 KB

    const int tid = threadIdx.x;
    const int w = tid >> 5, l = tid & 31;
    const int r = l >> 2, c = l & 3;
    const int b = blockIdx.x >> 4, it = blockIdx.x & 15;
    const int i0 = it * 8;
    const int f0 = w * 32;

    // ---- preload Wf fragments (k padded to 32) + bias pairs ----
    uint32_t B[4][4][2];
    float2 bfv[4];
    #pragma unroll
    for (int nb = 0; nb < 4; nb++) {
        const int fr = f0 + nb * 8 + r;
        #pragma unroll
        for (int ks = 0; ks < 4; ks++) {
            int k0 = ks * 8 + c, k1 = k0 + 4;
            B[ks][nb][0] = f2tf(Wf[fr * EF + k0]);
            B[ks][nb][1] = (k1 < EF) ? f2tf(Wf[fr * EF + k1]) : 0u;
        }
        bfv[nb] = *(const float2*)(bf + f0 + nb * 8 + 2 * c);
    }

    // ---- stage em[b, i0:i0+8, :] once ----
    #pragma unroll
    for (int q = 0; q < 4; q++) {
        int idx = tid + q * 256;
        int i_l = idx >> 7, j = idx & 127;
        em_s[i_l * EMS + j] = edge_mask[((b * NA) + i0 + i_l) * NA + j];
    }
    // ---- zero the k=30,31 fragment slots once (staging never writes them)
    if (tid < 128) {
        int rr = tid, t = rr >> 4, rbit = (rr >> 3) & 1, r8 = rr & 7;
        int base = ((t * 4 + 3) * 32 + r8 * 4);
        a_frag[(base + 2) * 4 + (rbit | 2)] = 0u;   // k=30 (c=2,chalf=1)
        a_frag[(base + 3) * 4 + (rbit | 2)] = 0u;   // k=31 (c=3,chalf=1)
    }

    float acc[4][2] = {};

    #pragma unroll 1
    for (int jt = 0; jt < 8; jt++) {
        // ---- stage A into fragment order ----
        #pragma unroll
        for (int q = 0; q < 8; q++) {
            int idx = tid + q * 256;
            if (idx < 1920) {
                int i_l = idx / 240;
                int rem = idx - i_l * 240;
                int jj = rem / 15;
                int p  = rem - jj * 15;
                const float2 v = *(const float2*)(
                    e + ((size_t)((b * NA + i0 + i_l) * NA) + jt * 16 + jj) * EF + 2 * p);
                int rr = jj * 8 + i_l;
                int t = rr >> 4, rbit = (rr >> 3) & 1, r8 = rr & 7;
                int ks = p >> 2, kin = (2 * p) & 7;
                int c0 = kin & 3, chalf = kin >> 2;
                int slot = ((t * 4 + ks) * 32 + r8 * 4 + c0) * 4 + (rbit | (chalf << 1));
                a_frag[slot]     = f2tf(v.x);
                a_frag[slot + 4] = f2tf(v.y);   // next c, same reg
            }
        }
        // ---- stage h[b, jt*16:+16, :] parity-interleaved ----
        #pragma unroll
        for (int q = 0; q < 4; q++) {
            int idx = tid + q * 256;
            int jj = idx >> 6, fq = idx & 63;
            float4 v = *(const float4*)(hbuf + (size_t)(b * NA + jt * 16 + jj) * HD + fq * 4);
            float* d = hpair + (jj >> 1) * 512 + fq * 8 + (jj & 1);
            d[0] = v.x; d[2] = v.y; d[4] = v.z; d[6] = v.w;
        }
        __syncthreads();

        #pragma unroll
        for (int t = 0; t < 8; t++) {
            const float2 emv = *(const float2*)(em_s + r * EMS + jt * 16 + 2 * t);
            float C[4][4];
            #pragma unroll
            for (int nb = 0; nb < 4; nb++) {
                C[nb][0] = bfv[nb].x; C[nb][1] = bfv[nb].y;
                C[nb][2] = bfv[nb].x; C[nb][3] = bfv[nb].y;
            }
            #pragma unroll
            for (int ks = 0; ks < 4; ks++) {
                uint4 av = *(const uint4*)(a_frag + ((t * 4 + ks) * 32 + l) * 4);
                #pragma unroll
                for (int nb = 0; nb < 4; nb++)
                    mma_tf32(C[nb], av.x, av.y, av.z, av.w, B[ks][nb][0], B[ks][nb][1]);
            }
            #pragma unroll
            for (int nb = 0; nb < 4; nb++) {
                // hv = {h[2t][f], h[2t+1][f], h[2t][f+1], h[2t+1][f+1]}
                float4 hv = *(const float4*)(hpair + t * 512 + (f0 + nb * 8 + 2 * c) * 2);
                float s0 = selu_f(C[nb][0]) * emv.x;   // (j=2t,   f)
                float s1 = selu_f(C[nb][1]) * emv.x;   // (j=2t,   f+1)
                float s2 = selu_f(C[nb][2]) * emv.y;   // (j=2t+1, f)
                float s3 = selu_f(C[nb][3]) * emv.y;   // (j=2t+1, f+1)
                acc[nb][0] = fmaf(s0, hv.x, fmaf(s2, hv.y, acc[nb][0]));
                acc[nb][1] = fmaf(s1, hv.z, fmaf(s3, hv.w, acc[nb][1]));
            }
        }
        __syncthreads();
    }

    // ---- write h1: lane owns (i = i0 + r) x 4 f-pairs ----
    #pragma unroll
    for (int nb = 0; nb < 4; nb++) {
        const int f = f0 + nb * 8 + 2 * c;
        *(float2*)(g_h1 + (size_t)(b * NA + i0 + r) * HD + f) =
            make_float2(acc[nb][0], acc[nb][1]);
    }
}

// -------------------------------------------------------------------------
// Kernel 2 (reverted to proven R3 config, 18.4 us): out = selu(z@Ww^T+bw)*nm+h
// GEMM M=2048, K=512, N=256. Grid 256 = 64 rb x 4 fb; CTA = 32 rows x 64 f.
// 8 warps: rt = w&1 (16-row half), fh = w>>1 (16-f quarter), nb=2.
// K in 8 chunks of 64; z stride 68 (bank 4r+c), w stride 73 (bank 8c+r).
// Bias folded into accumulator init.
// -------------------------------------------------------------------------
#define ZS 68
#define WS2 73

__global__ __launch_bounds__(256) void efconv_k2(
    const float* __restrict__ hbuf, const float* __restrict__ node_mask,
    const float* __restrict__ Ww, const float* __restrict__ bw,
    float* __restrict__ out)
{
    __shared__ uint32_t z_s[32 * ZS];   // [32 rows][68]
    __shared__ uint32_t w_s[64 * WS2];  // [64 k][73] (k-major, 64 f)

    const int tid = threadIdx.x;
    const int w = tid >> 5, l = tid & 31;
    const int r = l >> 2, c = l & 3;
    const int rb = blockIdx.x >> 2, fb = blockIdx.x & 3;
    const int row0 = rb * 32;
    const int rt = w & 1, fh = w >> 1;

    float C[2][4];
    #pragma unroll
    for (int nb = 0; nb < 2; nb++) {
        float2 bv = *(const float2*)(bw + fb * 64 + fh * 16 + nb * 8 + 2 * c);
        C[nb][0] = bv.x; C[nb][1] = bv.y; C[nb][2] = bv.x; C[nb][3] = bv.y;
    }

    #pragma unroll 1
    for (int kc = 0; kc < 8; kc++) {
        const float* zsrc = (kc < 4) ? hbuf : g_h1;
        const int cb = (kc & 3) * 64;
        // stage z: 32 rows x 64 k (2 float4 / thread, coalesced)
        #pragma unroll
        for (int q = 0; q < 2; q++) {
            int idx = tid + q * 256;
            int rr = idx >> 4, kq = idx & 15;
            float4 v = *(const float4*)(zsrc + (size_t)(row0 + rr) * HD + cb + kq * 4);
            uint32_t* d = z_s + rr * ZS + kq * 4;
            d[0] = f2tf(v.x); d[1] = f2tf(v.y); d[2] = f2tf(v.z); d[3] = f2tf(v.w);
        }
        // stage Ww chunk transposed: 64 f x 64 k -> w_s[k][f]
        #pragma unroll
        for (int q = 0; q < 4; q++) {
            int idx = tid + q * 256;
            int ff = idx >> 4, kq = idx & 15;
            float4 v = *(const float4*)(Ww + (size_t)(fb * 64 + ff) * (2 * HD) + kc * 64 + kq * 4);
            w_s[(kq * 4 + 0) * WS2 + ff] = f2tf(v.x);
            w_s[(kq * 4 + 1) * WS2 + ff] = f2tf(v.y);
            w_s[(kq * 4 + 2) * WS2 + ff] = f2tf(v.z);
            w_s[(kq * 4 + 3) * WS2 + ff] = f2tf(v.w);
        }
        __syncthreads();

        #pragma unroll
        for (int ks = 0; ks < 8; ks++) {
            const uint32_t* ar = z_s + (rt * 16 + r) * ZS + ks * 8 + c;
            uint32_t a0 = ar[0], a2 = ar[4];
            uint32_t a1 = ar[8 * ZS], a3 = ar[8 * ZS + 4];
            #pragma unroll
            for (int nb = 0; nb < 2; nb++) {
                uint32_t b0 = w_s[(ks * 8 + c) * WS2     + fh * 16 + nb * 8 + r];
                uint32_t b1 = w_s[(ks * 8 + c + 4) * WS2 + fh * 16 + nb * 8 + r];
                mma_tf32(C[nb], a0, a1, a2, a3, b0, b1);
            }
        }
        __syncthreads();
    }

    // ---- epilogue: selu(D) * nm + h (bias already in C) ----
    const int rg0 = row0 + rt * 16 + r, rg1 = rg0 + 8;
    const float nm0 = node_mask[rg0], nm1 = node_mask[rg1];
    #pragma unroll
    for (int nb = 0; nb < 2; nb++) {
        int f = fb * 64 + fh * 16 + nb * 8 + 2 * c;
        float2 h0 = *(const float2*)(hbuf + (size_t)rg0 * HD + f);
        float2 h1 = *(const float2*)(hbuf + (size_t)rg1 * HD + f);
        float2 o0, o1;
        o0.x = selu_f(C[nb][0]) * nm0 + h0.x;
        o0.y = selu_f(C[nb][1]) * nm0 + h0.y;
        o1.x = selu_f(C[nb][2]) * nm1 + h1.x;
        o1.y = selu_f(C[nb][3]) * nm1 + h1.y;
        *(float2*)(out + (size_t)rg0 * HD + f) = o0;
        *(float2*)(out + (size_t)rg1 * HD + f) = o1;
    }
}

extern "C" void kernel_launch(void* const* d_in, const int* in_sizes, int n_in,
                              void* d_out, int out_size)
{
    const float* h   = (const float*)d_in[0];   // (16,128,256)
    const float* e   = (const float*)d_in[1];   // (16,128,128,30)
    const float* nm  = (const float*)d_in[2];   // (16,128,1)
    const float* em  = (const float*)d_in[3];   // (16,128,128,1)
    const float* Wf  = (const float*)d_in[4];   // (256,30)
    const float* bf  = (const float*)d_in[5];   // (256,)
    const float* Ww  = (const float*)d_in[6];   // (256,512)
    const float* bw  = (const float*)d_in[7];   // (256,)
    float* out = (float*)d_out;                  // (16,128,256)

    efconv_k1<<<256, 256>>>(h, e, em, Wf, bf);
    efconv_k2<<<256, 256>>>(h, nm, Ww, bw, out);
}

// round 7
// speedup vs baseline: 2.2586x; 1.0745x over previous
#include <cuda_runtime.h>
#include <cstdint>

#define NBATCH 16
#define NA 128
#define HD 256
#define EF 30

#define SELU_SCALE 1.0507009873554805f
#define SELU_SA    1.7580993408473766f   // scale * alpha

// intermediate h1 (16*128*256 fp32 = 2 MB)
__device__ float g_h1[NBATCH * NA * HD];

__device__ __forceinline__ uint32_t f2tf(float x) {
    uint32_t u; asm("cvt.rna.tf32.f32 %0, %1;" : "=r"(u) : "f"(x)); return u;
}
__device__ __forceinline__ float selu_f(float d) {
    float e = __expf(d);
    return fmaf(SELU_SCALE, fmaxf(d, 0.f), fminf(fmaf(SELU_SA, e, -SELU_SA), 0.f));
}
__device__ __forceinline__ unsigned long long pack2(float a, float b) {
    unsigned long long v;
    asm("mov.b64 %0, {%1, %2};" : "=l"(v) : "f"(a), "f"(b));
    return v;
}
__device__ __forceinline__ unsigned long long mul2(unsigned long long a,
                                                   unsigned long long b) {
    unsigned long long d;
    asm("mul.rn.f32x2 %0, %1, %2;" : "=l"(d) : "l"(a), "l"(b));
    return d;
}
__device__ __forceinline__ unsigned long long fma2(unsigned long long a,
                                                   unsigned long long b,
                                                   unsigned long long c) {
    unsigned long long d;
    asm("fma.rn.f32x2 %0, %1, %2, %3;" : "=l"(d) : "l"(a), "l"(b), "l"(c));
    return d;
}
__device__ __forceinline__ void unpack2(unsigned long long v, float& a, float& b) {
    asm("mov.b64 {%0, %1}, %2;" : "=f"(a), "=f"(b) : "l"(v));
}
__device__ __forceinline__ void mma_tf32(float c[4],
                                         uint32_t a0, uint32_t a1, uint32_t a2, uint32_t a3,
                                         uint32_t b0, uint32_t b1) {
    asm volatile(
        "mma.sync.aligned.m16n8k8.row.col.f32.tf32.tf32.f32 "
        "{%0,%1,%2,%3}, {%4,%5,%6,%7}, {%8,%9}, {%0,%1,%2,%3};"
        : "+f"(c[0]), "+f"(c[1]), "+f"(c[2]), "+f"(c[3])
        : "r"(a0), "r"(a1), "r"(a2), "r"(a3), "r"(b0), "r"(b1));
}

// =========================================================================
// Kernel 1: CTA = (b, i-tile of 8), full 256 f. grid = 256. Double-buffered
// j-stages of 16: stage(jt+1) LDGs issued before compute(jt); ONE sync/iter.
// A in fragment order (1 LDS.128 -> 4 mma regs); h as [t][parity][f]
// (LDS.64 pairs, f32x2 packed epilogue); em staged once.
// =========================================================================
#define EMS 132
#define K1_AFW  4096              // words per a_frag buffer (32*32*4)
#define K1_HPW  4096              // words per hpair buffer (8*512)
#define K1_SMEM ((2*K1_AFW + 2*K1_HPW + 8*EMS) * 4)

__device__ __forceinline__ void k1_stage(
    int tid, int b, int i0, int jt,
    const float* __restrict__ e, const float* __restrict__ hbuf,
    uint32_t* __restrict__ af, float* __restrict__ hp)
{
    // A (e tile) -> fragment order
    #pragma unroll
    for (int q = 0; q < 8; q++) {
        int idx = tid + q * 256;
        if (idx < 1920) {
            int i_l = idx / 240;
            int rem = idx - i_l * 240;
            int jj = rem / 15;
            int p  = rem - jj * 15;
            const float2 v = *(const float2*)(
                e + ((size_t)((b * NA + i0 + i_l) * NA) + jt * 16 + jj) * EF + 2 * p);
            int rr = jj * 8 + i_l;
            int t = rr >> 4, rbit = (rr >> 3) & 1, r8 = rr & 7;
            int ks = p >> 2, kin = (2 * p) & 7;
            int c0 = kin & 3, chalf = kin >> 2;
            int slot = ((t * 4 + ks) * 32 + r8 * 4 + c0) * 4 + (rbit | (chalf << 1));
            af[slot]     = f2tf(v.x);
            af[slot + 4] = f2tf(v.y);
        }
    }
    // h tile -> [t][parity][f]
    #pragma unroll
    for (int q = 0; q < 4; q++) {
        int idx = tid + q * 256;
        int jj = idx >> 6, fq = idx & 63;
        float4 v = *(const float4*)(hbuf + (size_t)(b * NA + jt * 16 + jj) * HD + fq * 4);
        *(float4*)(hp + (jj >> 1) * 512 + (jj & 1) * 256 + fq * 4) = v;
    }
}

__global__ __launch_bounds__(256, 2) void efconv_k1(
    const float* __restrict__ hbuf, const float* __restrict__ e,
    const float* __restrict__ edge_mask, const float* __restrict__ Wf,
    const float* __restrict__ bf)
{
    extern __shared__ uint32_t sm1[];
    uint32_t* afb[2] = { sm1, sm1 + K1_AFW };
    float*    hpb[2] = { (float*)(sm1 + 2 * K1_AFW),
                         (float*)(sm1 + 2 * K1_AFW + K1_HPW) };
    float*    em_s   = (float*)(sm1 + 2 * K1_AFW + 2 * K1_HPW);

    const int tid = threadIdx.x;
    const int w = tid >> 5, l = tid & 31;
    const int r = l >> 2, c = l & 3;
    const int b = blockIdx.x >> 4, it = blockIdx.x & 15;
    const int i0 = it * 8;
    const int f0 = w * 32;

    // ---- preload Wf fragments + bias pairs ----
    uint32_t B[4][4][2];
    float2 bfv[4];
    #pragma unroll
    for (int nb = 0; nb < 4; nb++) {
        const int fr = f0 + nb * 8 + r;
        #pragma unroll
        for (int ks = 0; ks < 4; ks++) {
            int k0 = ks * 8 + c, k1 = k0 + 4;
            B[ks][nb][0] = f2tf(Wf[fr * EF + k0]);
            B[ks][nb][1] = (k1 < EF) ? f2tf(Wf[fr * EF + k1]) : 0u;
        }
        bfv[nb] = *(const float2*)(bf + f0 + nb * 8 + 2 * c);
    }

    // ---- em once ----
    #pragma unroll
    for (int q = 0; q < 4; q++) {
        int idx = tid + q * 256;
        int i_l = idx >> 7, j = idx & 127;
        em_s[i_l * EMS + j] = edge_mask[((b * NA) + i0 + i_l) * NA + j];
    }
    // ---- zero k=30,31 fragment slots in BOTH buffers ----
    if (tid < 128) {
        int rr = tid, t = rr >> 4, rbit = (rr >> 3) & 1, r8 = rr & 7;
        int base = ((t * 4 + 3) * 32 + r8 * 4);
        #pragma unroll
        for (int bu = 0; bu < 2; bu++) {
            afb[bu][(base + 2) * 4 + (rbit | 2)] = 0u;
            afb[bu][(base + 3) * 4 + (rbit | 2)] = 0u;
        }
    }

    k1_stage(tid, b, i0, 0, e, hbuf, afb[0], hpb[0]);
    __syncthreads();

    unsigned long long acc2[4] = {};

    #pragma unroll 1
    for (int jt = 0; jt < 8; jt++) {
        const int buf = jt & 1;
        if (jt < 7)
            k1_stage(tid, b, i0, jt + 1, e, hbuf, afb[buf ^ 1], hpb[buf ^ 1]);

        const uint32_t* af = afb[buf];
        const float*    hp = hpb[buf];

        #pragma unroll
        for (int t = 0; t < 8; t++) {
            const float2 emv = *(const float2*)(em_s + r * EMS + jt * 16 + 2 * t);
            const unsigned long long em0 = pack2(emv.x, emv.x);
            const unsigned long long em1 = pack2(emv.y, emv.y);
            float C[4][4];
            #pragma unroll
            for (int nb = 0; nb < 4; nb++) {
                C[nb][0] = bfv[nb].x; C[nb][1] = bfv[nb].y;
                C[nb][2] = bfv[nb].x; C[nb][3] = bfv[nb].y;
            }
            #pragma unroll
            for (int ks = 0; ks < 4; ks++) {
                uint4 av = *(const uint4*)(af + ((t * 4 + ks) * 32 + l) * 4);
                #pragma unroll
                for (int nb = 0; nb < 4; nb++)
                    mma_tf32(C[nb], av.x, av.y, av.z, av.w, B[ks][nb][0], B[ks][nb][1]);
            }
            #pragma unroll
            for (int nb = 0; nb < 4; nb++) {
                const int fl = f0 + nb * 8 + 2 * c;
                unsigned long long h0 = *(const unsigned long long*)(hp + t * 512 + fl);
                unsigned long long h1 = *(const unsigned long long*)(hp + t * 512 + 256 + fl);
                unsigned long long s01 = mul2(pack2(selu_f(C[nb][0]), selu_f(C[nb][1])), em0);
                unsigned long long s23 = mul2(pack2(selu_f(C[nb][2]), selu_f(C[nb][3])), em1);
                acc2[nb] = fma2(s01, h0, acc2[nb]);
                acc2[nb] = fma2(s23, h1, acc2[nb]);
            }
        }
        __syncthreads();
    }

    // ---- write h1 ----
    #pragma unroll
    for (int nb = 0; nb < 4; nb++) {
        const int f = f0 + nb * 8 + 2 * c;
        float a0, a1; unpack2(acc2[nb], a0, a1);
        *(float2*)(g_h1 + (size_t)(b * NA + i0 + r) * HD + f) = make_float2(a0, a1);
    }
}

// =========================================================================
// Kernel 2: out = selu([h|h1] @ Ww^T + bw) * nm + h
// M=2048, K=512, N=256. Grid 256 = 64 rb x 4 fb; CTA = 32 rows x 64 f.
// Double-buffered K-chunks of 64: stage(kc+1) before compute(kc), 1 sync/it.
// z stride 68 (bank 4r+c), w stride 73 (bank 8c+r). Bias folded into C.
// =========================================================================
#define ZS 68
#define WS2 73
#define K2_ZW (32 * ZS)
#define K2_WW (64 * WS2)
#define K2_SMEM ((2*K2_ZW + 2*K2_WW) * 4)

__device__ __forceinline__ void k2_stage(
    int tid, int row0, int fb, int kc,
    const float* __restrict__ hbuf, const float* __restrict__ Ww,
    uint32_t* __restrict__ zs, uint32_t* __restrict__ ws)
{
    const float* zsrc = (kc < 4) ? hbuf : g_h1;
    const int cb = (kc & 3) * 64;
    #pragma unroll
    for (int q = 0; q < 2; q++) {
        int idx = tid + q * 256;
        int rr = idx >> 4, kq = idx & 15;
        float4 v = *(const float4*)(zsrc + (size_t)(row0 + rr) * HD + cb + kq * 4);
        uint32_t* d = zs + rr * ZS + kq * 4;
        d[0] = f2tf(v.x); d[1] = f2tf(v.y); d[2] = f2tf(v.z); d[3] = f2tf(v.w);
    }
    #pragma unroll
    for (int q = 0; q < 4; q++) {
        int idx = tid + q * 256;
        int ff = idx >> 4, kq = idx & 15;
        float4 v = *(const float4*)(Ww + (size_t)(fb * 64 + ff) * (2 * HD) + kc * 64 + kq * 4);
        ws[(kq * 4 + 0) * WS2 + ff] = f2tf(v.x);
        ws[(kq * 4 + 1) * WS2 + ff] = f2tf(v.y);
        ws[(kq * 4 + 2) * WS2 + ff] = f2tf(v.z);
        ws[(kq * 4 + 3) * WS2 + ff] = f2tf(v.w);
    }
}

__global__ __launch_bounds__(256) void efconv_k2(
    const float* __restrict__ hbuf, const float* __restrict__ node_mask,
    const float* __restrict__ Ww, const float* __restrict__ bw,
    float* __restrict__ out)
{
    extern __shared__ uint32_t sm2[];
    uint32_t* zsb[2] = { sm2, sm2 + K2_ZW };
    uint32_t* wsb[2] = { sm2 + 2 * K2_ZW, sm2 + 2 * K2_ZW + K2_WW };

    const int tid = threadIdx.x;
    const int w = tid >> 5, l = tid & 31;
    const int r = l >> 2, c = l & 3;
    const int rb = blockIdx.x >> 2, fb = blockIdx.x & 3;
    const int row0 = rb * 32;
    const int rt = w & 1, fh = w >> 1;

    float C[2][4];
    #pragma unroll
    for (int nb = 0; nb < 2; nb++) {
        float2 bv = *(const float2*)(bw + fb * 64 + fh * 16 + nb * 8 + 2 * c);
        C[nb][0] = bv.x; C[nb][1] = bv.y; C[nb][2] = bv.x; C[nb][3] = bv.y;
    }

    k2_stage(tid, row0, fb, 0, hbuf, Ww, zsb[0], wsb[0]);
    __syncthreads();

    #pragma unroll 1
    for (int kc = 0; kc < 8; kc++) {
        const int buf = kc & 1;
        if (kc < 7)
            k2_stage(tid, row0, fb, kc + 1, hbuf, Ww, zsb[buf ^ 1], wsb[buf ^ 1]);

        const uint32_t* z_s = zsb[buf];
        const uint32_t* w_s = wsb[buf];
        #pragma unroll
        for (int ks = 0; ks < 8; ks++) {
            const uint32_t* ar = z_s + (rt * 16 + r) * ZS + ks * 8 + c;
            uint32_t a0 = ar[0], a2 = ar[4];
            uint32_t a1 = ar[8 * ZS], a3 = ar[8 * ZS + 4];
            #pragma unroll
            for (int nb = 0; nb < 2; nb++) {
                uint32_t b0 = w_s[(ks * 8 + c) * WS2     + fh * 16 + nb * 8 + r];
                uint32_t b1 = w_s[(ks * 8 + c + 4) * WS2 + fh * 16 + nb * 8 + r];
                mma_tf32(C[nb], a0, a1, a2, a3, b0, b1);
            }
        }
        __syncthreads();
    }

    // ---- epilogue ----
    const int rg0 = row0 + rt * 16 + r, rg1 = rg0 + 8;
    const float nm0 = node_mask[rg0], nm1 = node_mask[rg1];
    #pragma unroll
    for (int nb = 0; nb < 2; nb++) {
        int f = fb * 64 + fh * 16 + nb * 8 + 2 * c;
        float2 h0 = *(const float2*)(hbuf + (size_t)rg0 * HD + f);
        float2 h1 = *(const float2*)(hbuf + (size_t)rg1 * HD + f);
        float2 o0, o1;
        o0.x = selu_f(C[nb][0]) * nm0 + h0.x;
        o0.y = selu_f(C[nb][1]) * nm0 + h0.y;
        o1.x = selu_f(C[nb][2]) * nm1 + h1.x;
        o1.y = selu_f(C[nb][3]) * nm1 + h1.y;
        *(float2*)(out + (size_t)rg0 * HD + f) = o0;
        *(float2*)(out + (size_t)rg1 * HD + f) = o1;
    }
}

extern "C" void kernel_launch(void* const* d_in, const int* in_sizes, int n_in,
                              void* d_out, int out_size)
{
    const float* h   = (const float*)d_in[0];   // (16,128,256)
    const float* e   = (const float*)d_in[1];   // (16,128,128,30)
    const float* nm  = (const float*)d_in[2];   // (16,128,1)
    const float* em  = (const float*)d_in[3];   // (16,128,128,1)
    const float* Wf  = (const float*)d_in[4];   // (256,30)
    const float* bf  = (const float*)d_in[5];   // (256,)
    const float* Ww  = (const float*)d_in[6];   // (256,512)
    const float* bw  = (const float*)d_in[7];   // (256,)
    float* out = (float*)d_out;                  // (16,128,256)

    cudaFuncSetAttribute(efconv_k1, cudaFuncAttributeMaxDynamicSharedMemorySize, K1_SMEM);
    cudaFuncSetAttribute(efconv_k2, cudaFuncAttributeMaxDynamicSharedMemorySize, K2_SMEM);

    efconv_k1<<<256, 256, K1_SMEM>>>(h, e, em, Wf, bf);
    efconv_k2<<<256, 256, K2_SMEM>>>(h, nm, Ww, bw, out);
}

// round 8
// speedup vs baseline: 2.3814x; 1.0544x over previous
#include <cuda_runtime.h>
#include <cstdint>

#define NBATCH 16
#define NA 128
#define HD 256
#define EF 30

#define SELU_SCALE 1.0507009873554805f
#define SELU_SA    1.7580993408473766f   // scale * alpha

// intermediate h1 (16*128*256 fp32 = 2 MB)
__device__ float g_h1[NBATCH * NA * HD];

__device__ __forceinline__ uint32_t f2tf(float x) {
    uint32_t u; asm("cvt.rna.tf32.f32 %0, %1;" : "=r"(u) : "f"(x)); return u;
}
__device__ __forceinline__ float selu_f(float d) {
    float e = __expf(d);
    return fmaf(SELU_SCALE, fmaxf(d, 0.f), fminf(fmaf(SELU_SA, e, -SELU_SA), 0.f));
}
__device__ __forceinline__ unsigned long long pack2(float a, float b) {
    unsigned long long v;
    asm("mov.b64 %0, {%1, %2};" : "=l"(v) : "f"(a), "f"(b));
    return v;
}
__device__ __forceinline__ unsigned long long mul2(unsigned long long a,
                                                   unsigned long long b) {
    unsigned long long d;
    asm("mul.rn.f32x2 %0, %1, %2;" : "=l"(d) : "l"(a), "l"(b));
    return d;
}
__device__ __forceinline__ unsigned long long fma2(unsigned long long a,
                                                   unsigned long long b,
                                                   unsigned long long c) {
    unsigned long long d;
    asm("fma.rn.f32x2 %0, %1, %2, %3;" : "=l"(d) : "l"(a), "l"(b), "l"(c));
    return d;
}
__device__ __forceinline__ void unpack2(unsigned long long v, float& a, float& b) {
    asm("mov.b64 {%0, %1}, %2;" : "=f"(a), "=f"(b) : "l"(v));
}
__device__ __forceinline__ void mma_tf32(float c[4],
                                         uint32_t a0, uint32_t a1, uint32_t a2, uint32_t a3,
                                         uint32_t b0, uint32_t b1) {
    asm volatile(
        "mma.sync.aligned.m16n8k8.row.col.f32.tf32.tf32.f32 "
        "{%0,%1,%2,%3}, {%4,%5,%6,%7}, {%8,%9}, {%0,%1,%2,%3};"
        : "+f"(c[0]), "+f"(c[1]), "+f"(c[2]), "+f"(c[3])
        : "r"(a0), "r"(a1), "r"(a2), "r"(a3), "r"(b0), "r"(b1));
}

// =========================================================================
// Kernel 1: CTA = (b, i-tile of 4), full 256 f. grid = 16*32 = 512.
// A rows rr = jj*4 + i_l (j-major): m16 tile t covers jj in [4t,4t+4),
// lane row r -> (jj&3 = r>>2, i = r&3); rows r and r+8 share i, differ by
// jj+... C[0,1] -> jj = t*4+(r>>2); C[2,3] -> jj = t*4+2+(r>>2).
// Each output (i,f) accumulated by lanes l and l^16 -> one shfl_xor(16).
// A in PADDED fragment order (block stride 132 words: ~conflict-free STS,
// LDS.128 reads). h as hq[t][jj&3][f] (LDS.64 broadcast). Double-buffered.
// =========================================================================
#define EMS 132
#define K1_AFW (16 * 132)          // 4t x 4ks blocks, 132 words each
#define K1_HW  4096                // 16 j x 256 f
#define K1_SMEM ((2*K1_AFW + 2*K1_HW + 4*EMS) * 4)

__device__ __forceinline__ void k1_stage(
    int tid, int b, int i0, int jt,
    const float* __restrict__ e, const float* __restrict__ hbuf,
    uint32_t* __restrict__ af, float* __restrict__ hq)
{
    // A (e tile: 4 i x 16 j x 30 k) -> padded fragment order
    #pragma unroll
    for (int q = 0; q < 4; q++) {
        int idx = tid + q * 256;
        if (idx < 960) {
            int i_l = idx / 240;
            int rem = idx - i_l * 240;
            int jj = rem / 15;
            int p  = rem - jj * 15;
            const float2 v = *(const float2*)(
                e + ((size_t)((b * NA + i0 + i_l) * NA) + jt * 16 + jj) * EF + 2 * p);
            int rr = jj * 4 + i_l;                 // 0..63
            int t = rr >> 4, rloc = rr & 15;
            int rbit = rloc >> 3, r8 = rloc & 7;
            int ks = p >> 2, kin = (2 * p) & 7;
            int c0 = kin & 3, chalf = kin >> 2;
            int slot = (t * 4 + ks) * 132 + (r8 * 4 + c0) * 4 + (rbit | (chalf << 1));
            af[slot]     = f2tf(v.x);
            af[slot + 4] = f2tf(v.y);
        }
    }
    // h tile -> hq[t][jj&3][f]
    #pragma unroll
    for (int q = 0; q < 4; q++) {
        int idx = tid + q * 256;
        int jj = idx >> 6, fq = idx & 63;
        float4 v = *(const float4*)(hbuf + (size_t)(b * NA + jt * 16 + jj) * HD + fq * 4);
        *(float4*)(hq + (jj >> 2) * 1024 + (jj & 3) * 256 + fq * 4) = v;
    }
}

__global__ __launch_bounds__(256, 2) void efconv_k1(
    const float* __restrict__ hbuf, const float* __restrict__ e,
    const float* __restrict__ edge_mask, const float* __restrict__ Wf,
    const float* __restrict__ bf)
{
    extern __shared__ uint32_t sm1[];
    uint32_t* afb[2] = { sm1, sm1 + K1_AFW };
    float*    hqb[2] = { (float*)(sm1 + 2 * K1_AFW),
                         (float*)(sm1 + 2 * K1_AFW + K1_HW) };
    float*    em_s   = (float*)(sm1 + 2 * K1_AFW + 2 * K1_HW);

    const int tid = threadIdx.x;
    const int w = tid >> 5, l = tid & 31;
    const int r = l >> 2, c = l & 3;
    const int b = blockIdx.x >> 5, it = blockIdx.x & 31;
    const int i0 = it * 4;
    const int f0 = w * 32;

    // ---- preload Wf fragments + bias pairs ----
    uint32_t B[4][4][2];
    float2 bfv[4];
    #pragma unroll
    for (int nb = 0; nb < 4; nb++) {
        const int fr = f0 + nb * 8 + r;
        #pragma unroll
        for (int ks = 0; ks < 4; ks++) {
            int k0 = ks * 8 + c, k1 = k0 + 4;
            B[ks][nb][0] = f2tf(Wf[fr * EF + k0]);
            B[ks][nb][1] = (k1 < EF) ? f2tf(Wf[fr * EF + k1]) : 0u;
        }
        bfv[nb] = *(const float2*)(bf + f0 + nb * 8 + 2 * c);
    }

    // ---- em[b, i0:i0+4, :] once ----
    #pragma unroll
    for (int q = 0; q < 2; q++) {
        int idx = tid + q * 256;
        int i_l = idx >> 7, j = idx & 127;
        em_s[i_l * EMS + j] = edge_mask[((b * NA) + i0 + i_l) * NA + j];
    }
    // ---- zero k=30,31 fragment slots (both buffers) ----
    if (tid < 64) {
        int rr = tid, t = rr >> 4, rloc = rr & 15;
        int rbit = rloc >> 3, r8 = rloc & 7;
        int base = (t * 4 + 3) * 132 + r8 * 16;
        #pragma unroll
        for (int bu = 0; bu < 2; bu++) {
            afb[bu][base + 2 * 4 + (rbit | 2)] = 0u;   // k=30
            afb[bu][base + 3 * 4 + (rbit | 2)] = 0u;   // k=31
        }
    }

    k1_stage(tid, b, i0, 0, e, hbuf, afb[0], hqb[0]);
    __syncthreads();

    unsigned long long acc2[4] = {};

    #pragma unroll 1
    for (int jt = 0; jt < 8; jt++) {
        const int buf = jt & 1;
        if (jt < 7)
            k1_stage(tid, b, i0, jt + 1, e, hbuf, afb[buf ^ 1], hqb[buf ^ 1]);

        const uint32_t* af = afb[buf];
        const float*    hq = hqb[buf];

        #pragma unroll
        for (int t = 0; t < 4; t++) {
            const int qa = r >> 2;                     // jj&3 for C[0,1]
            const float em0 = em_s[(r & 3) * EMS + jt * 16 + t * 4 + qa];
            const float em1 = em_s[(r & 3) * EMS + jt * 16 + t * 4 + qa + 2];
            const unsigned long long em0p = pack2(em0, em0);
            const unsigned long long em1p = pack2(em1, em1);
            float C[4][4];
            #pragma unroll
            for (int nb = 0; nb < 4; nb++) {
                C[nb][0] = bfv[nb].x; C[nb][1] = bfv[nb].y;
                C[nb][2] = bfv[nb].x; C[nb][3] = bfv[nb].y;
            }
            #pragma unroll
            for (int ks = 0; ks < 4; ks++) {
                uint4 av = *(const uint4*)(af + (t * 4 + ks) * 132 + l * 4);
                #pragma unroll
                for (int nb = 0; nb < 4; nb++)
                    mma_tf32(C[nb], av.x, av.y, av.z, av.w, B[ks][nb][0], B[ks][nb][1]);
            }
            #pragma unroll
            for (int nb = 0; nb < 4; nb++) {
                const int fl = f0 + nb * 8 + 2 * c;
                unsigned long long h0 =
                    *(const unsigned long long*)(hq + t * 1024 + qa * 256 + fl);
                unsigned long long h1 =
                    *(const unsigned long long*)(hq + t * 1024 + (qa + 2) * 256 + fl);
                unsigned long long s01 = mul2(pack2(selu_f(C[nb][0]), selu_f(C[nb][1])), em0p);
                unsigned long long s23 = mul2(pack2(selu_f(C[nb][2]), selu_f(C[nb][3])), em1p);
                acc2[nb] = fma2(s01, h0, acc2[nb]);
                acc2[nb] = fma2(s23, h1, acc2[nb]);
            }
        }
        __syncthreads();
    }

    // ---- combine lane pairs (l, l^16) and write h1 ----
    #pragma unroll
    for (int nb = 0; nb < 4; nb++) {
        float a0, a1; unpack2(acc2[nb], a0, a1);
        a0 += __shfl_xor_sync(0xffffffffu, a0, 16);
        a1 += __shfl_xor_sync(0xffffffffu, a1, 16);
        if (l < 16) {
            const int f = f0 + nb * 8 + 2 * c;
            *(float2*)(g_h1 + (size_t)(b * NA + i0 + r) * HD + f) = make_float2(a0, a1);
        }
    }
}

// =========================================================================
// Kernel 2: out = selu([h|h1] @ Ww^T + bw) * nm + h
// M=2048, K=512, N=256. Grid 256 = 64 rb x 4 fb; CTA = 32 rows x 64 f.
// Double-buffered K-chunks of 64. FRAGMENT-ORDER smem:
//   zfrag[(rt*8+ks)*132 + lane*4 + reg]   -> 1 LDS.128/ks
//   wfrag[ks*516 + f*8 + c*2 + half]      -> 1 LDS.64/(ks,nb)
// Inner loop per ks: 1 LDS.128 + 2 LDS.64 + 2 mma (was 8 LDS.32 + 2 mma).
// =========================================================================
#define K2_ZW (16 * 132)
#define K2_WW (8 * 516)
#define K2_SMEM ((2*K2_ZW + 2*K2_WW) * 4)

__device__ __forceinline__ void k2_stage(
    int tid, int row0, int fb, int kc,
    const float* __restrict__ hbuf, const float* __restrict__ Ww,
    uint32_t* __restrict__ zf, uint32_t* __restrict__ wf)
{
    const float* zsrc = (kc < 4) ? hbuf : g_h1;
    const int cb = (kc & 3) * 64;
    // z: 32 rows x 64 k -> fragment order
    #pragma unroll
    for (int q = 0; q < 2; q++) {
        int idx = tid + q * 256;
        int rr = idx >> 4, kq = idx & 15;
        float4 v = *(const float4*)(zsrc + (size_t)(row0 + rr) * HD + cb + kq * 4);
        int rt = rr >> 4, rloc = rr & 15;
        int rbit = rloc >> 3, r8 = rloc & 7;
        int ks = kq >> 1, chalf = kq & 1;
        int reg = rbit | (chalf << 1);
        uint32_t* d = zf + (rt * 8 + ks) * 132 + r8 * 16 + reg;
        d[0]  = f2tf(v.x);   // c0 = 0
        d[4]  = f2tf(v.y);   // c0 = 1
        d[8]  = f2tf(v.z);   // c0 = 2
        d[12] = f2tf(v.w);   // c0 = 3
    }
    // Ww: 64 f x 64 k -> pair-fragment order
    #pragma unroll
    for (int q = 0; q < 4; q++) {
        int idx = tid + q * 256;
        int ff = idx >> 4, kq = idx & 15;
        float4 v = *(const float4*)(Ww + (size_t)(fb * 64 + ff) * (2 * HD) + kc * 64 + kq * 4);
        int ks = kq >> 1, half = kq & 1;
        uint32_t* d = wf + ks * 516 + ff * 8 + half;
        d[0] = f2tf(v.x);   // c = 0
        d[2] = f2tf(v.y);   // c = 1
        d[4] = f2tf(v.z);   // c = 2
        d[6] = f2tf(v.w);   // c = 3
    }
}

__global__ __launch_bounds__(256) void efconv_k2(
    const float* __restrict__ hbuf, const float* __restrict__ node_mask,
    const float* __restrict__ Ww, const float* __restrict__ bw,
    float* __restrict__ out)
{
    extern __shared__ uint32_t sm2[];
    uint32_t* zfb[2] = { sm2, sm2 + K2_ZW };
    uint32_t* wfb[2] = { sm2 + 2 * K2_ZW, sm2 + 2 * K2_ZW + K2_WW };

    const int tid = threadIdx.x;
    const int w = tid >> 5, l = tid & 31;
    const int r = l >> 2, c = l & 3;
    const int rb = blockIdx.x >> 2, fb = blockIdx.x & 3;
    const int row0 = rb * 32;
    const int rt = w & 1, fh = w >> 1;

    float C[2][4];
    #pragma unroll
    for (int nb = 0; nb < 2; nb++) {
        float2 bv = *(const float2*)(bw + fb * 64 + fh * 16 + nb * 8 + 2 * c);
        C[nb][0] = bv.x; C[nb][1] = bv.y; C[nb][2] = bv.x; C[nb][3] = bv.y;
    }

    k2_stage(tid, row0, fb, 0, hbuf, Ww, zfb[0], wfb[0]);
    __syncthreads();

    #pragma unroll 1
    for (int kc = 0; kc < 8; kc++) {
        const int buf = kc & 1;
        if (kc < 7)
            k2_stage(tid, row0, fb, kc + 1, hbuf, Ww, zfb[buf ^ 1], wfb[buf ^ 1]);

        const uint32_t* zf = zfb[buf];
        const uint32_t* wf = wfb[buf];
        #pragma unroll
        for (int ks = 0; ks < 8; ks++) {
            uint4 av = *(const uint4*)(zf + (rt * 8 + ks) * 132 + l * 4);
            #pragma unroll
            for (int nb = 0; nb < 2; nb++) {
                const int fl = fh * 16 + nb * 8 + r;
                uint2 bb = *(const uint2*)(wf + ks * 516 + fl * 8 + c * 2);
                mma_tf32(C[nb], av.x, av.y, av.z, av.w, bb.x, bb.y);
            }
        }
        __syncthreads();
    }

    // ---- epilogue ----
    const int rg0 = row0 + rt * 16 + r, rg1 = rg0 + 8;
    const float nm0 = node_mask[rg0], nm1 = node_mask[rg1];
    #pragma unroll
    for (int nb = 0; nb < 2; nb++) {
        int f = fb * 64 + fh * 16 + nb * 8 + 2 * c;
        float2 h0 = *(const float2*)(hbuf + (size_t)rg0 * HD + f);
        float2 h1 = *(const float2*)(hbuf + (size_t)rg1 * HD + f);
        float2 o0, o1;
        o0.x = selu_f(C[nb][0]) * nm0 + h0.x;
        o0.y = selu_f(C[nb][1]) * nm0 + h0.y;
        o1.x = selu_f(C[nb][2]) * nm1 + h1.x;
        o1.y = selu_f(C[nb][3]) * nm1 + h1.y;
        *(float2*)(out + (size_t)rg0 * HD + f) = o0;
        *(float2*)(out + (size_t)rg1 * HD + f) = o1;
    }
}

extern "C" void kernel_launch(void* const* d_in, const int* in_sizes, int n_in,
                              void* d_out, int out_size)
{
    const float* h   = (const float*)d_in[0];   // (16,128,256)
    const float* e   = (const float*)d_in[1];   // (16,128,128,30)
    const float* nm  = (const float*)d_in[2];   // (16,128,1)
    const float* em  = (const float*)d_in[3];   // (16,128,128,1)
    const float* Wf  = (const float*)d_in[4];   // (256,30)
    const float* bf  = (const float*)d_in[5];   // (256,)
    const float* Ww  = (const float*)d_in[6];   // (256,512)
    const float* bw  = (const float*)d_in[7];   // (256,)
    float* out = (float*)d_out;                  // (16,128,256)

    cudaFuncSetAttribute(efconv_k1, cudaFuncAttributeMaxDynamicSharedMemorySize, K1_SMEM);
    cudaFuncSetAttribute(efconv_k2, cudaFuncAttributeMaxDynamicSharedMemorySize, K2_SMEM);

    efconv_k1<<<512, 256, K1_SMEM>>>(h, e, em, Wf, bf);
    efconv_k2<<<256, 256, K2_SMEM>>>(h, nm, Ww, bw, out);
}

// round 9
// speedup vs baseline: 2.4854x; 1.0437x over previous
#include <cuda_runtime.h>
#include <cstdint>

#define NBATCH 16
#define NA 128
#define HD 256
#define EF 30

#define SELU_SCALE 1.0507009873554805f
#define SELU_SA    1.7580993408473766f     // scale * alpha
#define LOG2E      1.4426950408889634f
#define K1LN2      (1.0507009873554805f * 0.69314718055994531f)  // scale*ln2

// intermediate h1 (16*128*256 fp32 = 2 MB)
__device__ float g_h1[NBATCH * NA * HD];

__device__ __forceinline__ uint32_t f2tf(float x) {
    uint32_t u; asm("cvt.rna.tf32.f32 %0, %1;" : "=r"(u) : "f"(x)); return u;
}
__device__ __forceinline__ float ex2f(float x) {
    float y; asm("ex2.approx.f32 %0, %1;" : "=f"(y) : "f"(x)); return y;
}
// input d2 = d * log2e (scale folded into weights); output = selu(d)
__device__ __forceinline__ float selu_l2(float d2) {
    float e = ex2f(d2);
    return fmaf(K1LN2, fmaxf(d2, 0.f), fminf(fmaf(SELU_SA, e, -SELU_SA), 0.f));
}
__device__ __forceinline__ float selu_f(float d) {
    float e = ex2f(d * LOG2E);
    return fmaf(SELU_SCALE, fmaxf(d, 0.f), fminf(fmaf(SELU_SA, e, -SELU_SA), 0.f));
}
__device__ __forceinline__ unsigned long long pack2(float a, float b) {
    unsigned long long v;
    asm("mov.b64 %0, {%1, %2};" : "=l"(v) : "f"(a), "f"(b));
    return v;
}
__device__ __forceinline__ unsigned long long mul2(unsigned long long a,
                                                   unsigned long long b) {
    unsigned long long d;
    asm("mul.rn.f32x2 %0, %1, %2;" : "=l"(d) : "l"(a), "l"(b));
    return d;
}
__device__ __forceinline__ unsigned long long fma2(unsigned long long a,
                                                   unsigned long long b,
                                                   unsigned long long c) {
    unsigned long long d;
    asm("fma.rn.f32x2 %0, %1, %2, %3;" : "=l"(d) : "l"(a), "l"(b), "l"(c));
    return d;
}
__device__ __forceinline__ void unpack2(unsigned long long v, float& a, float& b) {
    asm("mov.b64 {%0, %1}, %2;" : "=f"(a), "=f"(b) : "l"(v));
}
__device__ __forceinline__ void mma_tf32(float c[4],
                                         uint32_t a0, uint32_t a1, uint32_t a2, uint32_t a3,
                                         uint32_t b0, uint32_t b1) {
    asm volatile(
        "mma.sync.aligned.m16n8k8.row.col.f32.tf32.tf32.f32 "
        "{%0,%1,%2,%3}, {%4,%5,%6,%7}, {%8,%9}, {%0,%1,%2,%3};"
        : "+f"(c[0]), "+f"(c[1]), "+f"(c[2]), "+f"(c[3])
        : "r"(a0), "r"(a1), "r"(a2), "r"(a3), "r"(b0), "r"(b1));
}

// =========================================================================
// Kernel 1: CTA = (b, i-tile of 4, f-half of 128). grid = 16*32*2 = 1024.
// A rows rr = jj*4 + i_l (j-major, same layout as R8 - verified).
// GEMM weights pre-scaled by log2e: D = d*log2e -> selu needs no pre-FFMA.
// LDG-early / STS-late double-buffered pipeline, one sync per stage.
// A in padded fragment order (132-word blocks); h as hq[t][jj&3][f_local].
// Outputs folded across lane pairs (l, l^16) via one shfl_xor.
// =========================================================================
#define EMS 132
#define K1_AFW (16 * 132)          // 4t x 4ks blocks, 132 words each
#define K1_HW  (16 * 128)          // 16 j x 128 f_local

__global__ __launch_bounds__(256, 3) void efconv_k1(
    const float* __restrict__ hbuf, const float* __restrict__ e,
    const float* __restrict__ edge_mask, const float* __restrict__ Wf,
    const float* __restrict__ bf)
{
    __shared__ uint32_t afb[2][K1_AFW];   // 16.9 KB
    __shared__ float    hqb[2][K1_HW];    // 16 KB
    __shared__ float    em_s[4 * EMS];    //  2.1 KB

    const int tid = threadIdx.x;
    const int w = tid >> 5, l = tid & 31;
    const int r = l >> 2, c = l & 3;
    const int bid = blockIdx.x;
    const int fh = bid & 1, it = (bid >> 1) & 31, b = bid >> 6;
    const int i0 = it * 4;
    const int f0w = fh * 128 + w * 16;    // global f base of this warp
    const int flw = w * 16;               // local f base within the 128-half

    // ---- preload Wf fragments (x log2e) + bias pairs (x log2e) ----
    uint32_t B[4][2][2];
    float2 bfv[2];
    #pragma unroll
    for (int nb = 0; nb < 2; nb++) {
        const int fr = f0w + nb * 8 + r;
        #pragma unroll
        for (int ks = 0; ks < 4; ks++) {
            int k0 = ks * 8 + c, k1 = k0 + 4;
            B[ks][nb][0] = f2tf(Wf[fr * EF + k0] * LOG2E);
            B[ks][nb][1] = (k1 < EF) ? f2tf(Wf[fr * EF + k1] * LOG2E) : 0u;
        }
        float2 bv = *(const float2*)(bf + f0w + nb * 8 + 2 * c);
        bfv[nb] = make_float2(bv.x * LOG2E, bv.y * LOG2E);
    }

    // ---- em[b, i0:i0+4, :] once ----
    #pragma unroll
    for (int q = 0; q < 2; q++) {
        int idx = tid + q * 256;
        int i_l = idx >> 7, j = idx & 127;
        em_s[i_l * EMS + j] = edge_mask[((b * NA) + i0 + i_l) * NA + j];
    }
    // ---- zero k=30,31 fragment slots (both buffers) ----
    if (tid < 64) {
        int rr = tid, t = rr >> 4, rloc = rr & 15;
        int rbit = rloc >> 3, r8 = rloc & 7;
        int base = (t * 4 + 3) * 132 + r8 * 16;
        #pragma unroll
        for (int bu = 0; bu < 2; bu++) {
            afb[bu][base + 2 * 4 + (rbit | 2)] = 0u;   // k=30
            afb[bu][base + 3 * 4 + (rbit | 2)] = 0u;   // k=31
        }
    }

    // ---- prologue: stage jt = 0 ----
    {
        float2 va[4]; float4 vh[2];
        #pragma unroll
        for (int q = 0; q < 4; q++) {
            int idx = tid + q * 256;
            if (idx < 960) {
                int i_l = idx / 240, rem = idx - i_l * 240;
                int jj = rem / 15, p = rem - jj * 15;
                va[q] = *(const float2*)(
                    e + ((size_t)((b * NA + i0 + i_l) * NA) + jj) * EF + 2 * p);
            }
        }
        #pragma unroll
        for (int q = 0; q < 2; q++) {
            int idx = tid + q * 256;
            int jj = idx >> 5, fq = idx & 31;
            vh[q] = *(const float4*)(hbuf + (size_t)(b * NA + jj) * HD + fh * 128 + fq * 4);
        }
        #pragma unroll
        for (int q = 0; q < 4; q++) {
            int idx = tid + q * 256;
            if (idx < 960) {
                int i_l = idx / 240, rem = idx - i_l * 240;
                int jj = rem / 15, p = rem - jj * 15;
                int rr = jj * 4 + i_l;
                int t = rr >> 4, rloc = rr & 15;
                int rbit = rloc >> 3, r8 = rloc & 7;
                int ks = p >> 2, kin = (2 * p) & 7;
                int c0 = kin & 3, chalf = kin >> 2;
                int slot = (t * 4 + ks) * 132 + (r8 * 4 + c0) * 4 + (rbit | (chalf << 1));
                afb[0][slot]     = f2tf(va[q].x);
                afb[0][slot + 4] = f2tf(va[q].y);
            }
        }
        #pragma unroll
        for (int q = 0; q < 2; q++) {
            int idx = tid + q * 256;
            int jj = idx >> 5, fq = idx & 31;
            *(float4*)(hqb[0] + (jj >> 2) * 512 + (jj & 3) * 128 + fq * 4) = vh[q];
        }
    }
    __syncthreads();

    unsigned long long acc2[2] = {};

    #pragma unroll 1
    for (int jt = 0; jt < 8; jt++) {
        const int buf = jt & 1;

        // ---- prefetch stage jt+1 into registers (LDG only) ----
        float2 va[4]; float4 vh[2];
        if (jt < 7) {
            #pragma unroll
            for (int q = 0; q < 4; q++) {
                int idx = tid + q * 256;
                if (idx < 960) {
                    int i_l = idx / 240, rem = idx - i_l * 240;
                    int jj = rem / 15, p = rem - jj * 15;
                    va[q] = *(const float2*)(
                        e + ((size_t)((b * NA + i0 + i_l) * NA) + (jt + 1) * 16 + jj) * EF + 2 * p);
                }
            }
            #pragma unroll
            for (int q = 0; q < 2; q++) {
                int idx = tid + q * 256;
                int jj = idx >> 5, fq = idx & 31;
                vh[q] = *(const float4*)(
                    hbuf + (size_t)(b * NA + (jt + 1) * 16 + jj) * HD + fh * 128 + fq * 4);
            }
        }

        const uint32_t* af = afb[buf];
        const float*    hq = hqb[buf];

        // ---- compute stage jt ----
        #pragma unroll
        for (int t = 0; t < 4; t++) {
            const int qa = r >> 2;
            const float em0 = em_s[(r & 3) * EMS + jt * 16 + t * 4 + qa];
            const float em1 = em_s[(r & 3) * EMS + jt * 16 + t * 4 + qa + 2];
            const unsigned long long em0p = pack2(em0, em0);
            const unsigned long long em1p = pack2(em1, em1);
            float C[2][4];
            #pragma unroll
            for (int nb = 0; nb < 2; nb++) {
                C[nb][0] = bfv[nb].x; C[nb][1] = bfv[nb].y;
                C[nb][2] = bfv[nb].x; C[nb][3] = bfv[nb].y;
            }
            #pragma unroll
            for (int ks = 0; ks < 4; ks++) {
                uint4 av = *(const uint4*)(af + (t * 4 + ks) * 132 + l * 4);
                mma_tf32(C[0], av.x, av.y, av.z, av.w, B[ks][0][0], B[ks][0][1]);
                mma_tf32(C[1], av.x, av.y, av.z, av.w, B[ks][1][0], B[ks][1][1]);
            }
            #pragma unroll
            for (int nb = 0; nb < 2; nb++) {
                const int fl = flw + nb * 8 + 2 * c;
                unsigned long long h0 =
                    *(const unsigned long long*)(hq + t * 512 + qa * 128 + fl);
                unsigned long long h1 =
                    *(const unsigned long long*)(hq + t * 512 + (qa + 2) * 128 + fl);
                unsigned long long s01 = mul2(pack2(selu_l2(C[nb][0]), selu_l2(C[nb][1])), em0p);
                unsigned long long s23 = mul2(pack2(selu_l2(C[nb][2]), selu_l2(C[nb][3])), em1p);
                acc2[nb] = fma2(s01, h0, acc2[nb]);
                acc2[nb] = fma2(s23, h1, acc2[nb]);
            }
        }

        // ---- STS stage jt+1 + barrier ----
        if (jt < 7) {
            uint32_t* af1 = afb[buf ^ 1];
            float*    hq1 = hqb[buf ^ 1];
            #pragma unroll
            for (int q = 0; q < 4; q++) {
                int idx = tid + q * 256;
                if (idx < 960) {
                    int i_l = idx / 240, rem = idx - i_l * 240;
                    int jj = rem / 15, p = rem - jj * 15;
                    int rr = jj * 4 + i_l;
                    int t = rr >> 4, rloc = rr & 15;
                    int rbit = rloc >> 3, r8 = rloc & 7;
                    int ks = p >> 2, kin = (2 * p) & 7;
                    int c0 = kin & 3, chalf = kin >> 2;
                    int slot = (t * 4 + ks) * 132 + (r8 * 4 + c0) * 4 + (rbit | (chalf << 1));
                    af1[slot]     = f2tf(va[q].x);
                    af1[slot + 4] = f2tf(va[q].y);
                }
            }
            #pragma unroll
            for (int q = 0; q < 2; q++) {
                int idx = tid + q * 256;
                int jj = idx >> 5, fq = idx & 31;
                *(float4*)(hq1 + (jj >> 2) * 512 + (jj & 3) * 128 + fq * 4) = vh[q];
            }
            __syncthreads();
        }
    }

    // ---- combine lane pairs (l, l^16) and write h1 ----
    #pragma unroll
    for (int nb = 0; nb < 2; nb++) {
        float a0, a1; unpack2(acc2[nb], a0, a1);
        a0 += __shfl_xor_sync(0xffffffffu, a0, 16);
        a1 += __shfl_xor_sync(0xffffffffu, a1, 16);
        if (l < 16) {
            const int f = f0w + nb * 8 + 2 * c;
            *(float2*)(g_h1 + (size_t)(b * NA + i0 + r) * HD + f) = make_float2(a0, a1);
        }
    }
}

// =========================================================================
// Kernel 2: out = selu([h|h1] @ Ww^T + bw) * nm + h
// M=2048, K=512, N=256. Grid 256 = 64 rb x 4 fb; CTA = 32 rows x 64 f.
// LDG-early / STS-late double-buffered K-chunks of 64. Fragment-order smem
// (same mappings as R8 - verified). Bias folded into C.
// =========================================================================
#define K2_ZW (16 * 132)
#define K2_WW (8 * 516)
#define K2_SMEM ((2*K2_ZW + 2*K2_WW) * 4)

__global__ __launch_bounds__(256) void efconv_k2(
    const float* __restrict__ hbuf, const float* __restrict__ node_mask,
    const float* __restrict__ Ww, const float* __restrict__ bw,
    float* __restrict__ out)
{
    extern __shared__ uint32_t sm2[];
    uint32_t* zfb[2] = { sm2, sm2 + K2_ZW };
    uint32_t* wfb[2] = { sm2 + 2 * K2_ZW, sm2 + 2 * K2_ZW + K2_WW };

    const int tid = threadIdx.x;
    const int w = tid >> 5, l = tid & 31;
    const int r = l >> 2, c = l & 3;
    const int rb = blockIdx.x >> 2, fb = blockIdx.x & 3;
    const int row0 = rb * 32;
    const int rt = w & 1, fh = w >> 1;

    float C[2][4];
    #pragma unroll
    for (int nb = 0; nb < 2; nb++) {
        float2 bv = *(const float2*)(bw + fb * 64 + fh * 16 + nb * 8 + 2 * c);
        C[nb][0] = bv.x; C[nb][1] = bv.y; C[nb][2] = bv.x; C[nb][3] = bv.y;
    }

    // ---- prologue: stage kc = 0 ----
    {
        float4 zv[2], wv[4];
        #pragma unroll
        for (int q = 0; q < 2; q++) {
            int idx = tid + q * 256;
            int rr = idx >> 4, kq = idx & 15;
            zv[q] = *(const float4*)(hbuf + (size_t)(row0 + rr) * HD + kq * 4);
        }
        #pragma unroll
        for (int q = 0; q < 4; q++) {
            int idx = tid + q * 256;
            int ff = idx >> 4, kq = idx & 15;
            wv[q] = *(const float4*)(Ww + (size_t)(fb * 64 + ff) * (2 * HD) + kq * 4);
        }
        #pragma unroll
        for (int q = 0; q < 2; q++) {
            int idx = tid + q * 256;
            int rr = idx >> 4, kq = idx & 15;
            int rt2 = rr >> 4, rloc = rr & 15;
            int rbit = rloc >> 3, r8 = rloc & 7;
            int ks = kq >> 1, chalf = kq & 1;
            uint32_t* d = zfb[0] + (rt2 * 8 + ks) * 132 + r8 * 16 + (rbit | (chalf << 1));
            d[0] = f2tf(zv[q].x); d[4] = f2tf(zv[q].y);
            d[8] = f2tf(zv[q].z); d[12] = f2tf(zv[q].w);
        }
        #pragma unroll
        for (int q = 0; q < 4; q++) {
            int idx = tid + q * 256;
            int ff = idx >> 4, kq = idx & 15;
            int ks = kq >> 1, half = kq & 1;
            uint32_t* d = wfb[0] + ks * 516 + ff * 8 + half;
            d[0] = f2tf(wv[q].x); d[2] = f2tf(wv[q].y);
            d[4] = f2tf(wv[q].z); d[6] = f2tf(wv[q].w);
        }
    }
    __syncthreads();

    #pragma unroll 1
    for (int kc = 0; kc < 8; kc++) {
        const int buf = kc & 1;

        // ---- prefetch stage kc+1 (LDG only) ----
        float4 zv[2], wv[4];
        if (kc < 7) {
            const float* zsrc = (kc + 1 < 4) ? hbuf : g_h1;
            const int cb = ((kc + 1) & 3) * 64;
            #pragma unroll
            for (int q = 0; q < 2; q++) {
                int idx = tid + q * 256;
                int rr = idx >> 4, kq = idx & 15;
                zv[q] = *(const float4*)(zsrc + (size_t)(row0 + rr) * HD + cb + kq * 4);
            }
            #pragma unroll
            for (int q = 0; q < 4; q++) {
                int idx = tid + q * 256;
                int ff = idx >> 4, kq = idx & 15;
                wv[q] = *(const float4*)(
                    Ww + (size_t)(fb * 64 + ff) * (2 * HD) + (kc + 1) * 64 + kq * 4);
            }
        }

        // ---- compute stage kc ----
        const uint32_t* zf = zfb[buf];
        const uint32_t* wf = wfb[buf];
        #pragma unroll
        for (int ks = 0; ks < 8; ks++) {
            uint4 av = *(const uint4*)(zf + (rt * 8 + ks) * 132 + l * 4);
            #pragma unroll
            for (int nb = 0; nb < 2; nb++) {
                const int fl = fh * 16 + nb * 8 + r;
                uint2 bb = *(const uint2*)(wf + ks * 516 + fl * 8 + c * 2);
                mma_tf32(C[nb], av.x, av.y, av.z, av.w, bb.x, bb.y);
            }
        }

        // ---- STS stage kc+1 + barrier ----
        if (kc < 7) {
            uint32_t* zf1 = zfb[buf ^ 1];
            uint32_t* wf1 = wfb[buf ^ 1];
            #pragma unroll
            for (int q = 0; q < 2; q++) {
                int idx = tid + q * 256;
                int rr = idx >> 4, kq = idx & 15;
                int rt2 = rr >> 4, rloc = rr & 15;
                int rbit = rloc >> 3, r8 = rloc & 7;
                int ks = kq >> 1, chalf = kq & 1;
                uint32_t* d = zf1 + (rt2 * 8 + ks) * 132 + r8 * 16 + (rbit | (chalf << 1));
                d[0] = f2tf(zv[q].x); d[4] = f2tf(zv[q].y);
                d[8] = f2tf(zv[q].z); d[12] = f2tf(zv[q].w);
            }
            #pragma unroll
            for (int q = 0; q < 4; q++) {
                int idx = tid + q * 256;
                int ff = idx >> 4, kq = idx & 15;
                int ks = kq >> 1, half = kq & 1;
                uint32_t* d = wf1 + ks * 516 + ff * 8 + half;
                d[0] = f2tf(wv[q].x); d[2] = f2tf(wv[q].y);
                d[4] = f2tf(wv[q].z); d[6] = f2tf(wv[q].w);
            }
            __syncthreads();
        }
    }

    // ---- epilogue ----
    const int rg0 = row0 + rt * 16 + r, rg1 = rg0 + 8;
    const float nm0 = node_mask[rg0], nm1 = node_mask[rg1];
    #pragma unroll
    for (int nb = 0; nb < 2; nb++) {
        int f = fb * 64 + fh * 16 + nb * 8 + 2 * c;
        float2 h0 = *(const float2*)(hbuf + (size_t)rg0 * HD + f);
        float2 h1 = *(const float2*)(hbuf + (size_t)rg1 * HD + f);
        float2 o0, o1;
        o0.x = selu_f(C[nb][0]) * nm0 + h0.x;
        o0.y = selu_f(C[nb][1]) * nm0 + h0.y;
        o1.x = selu_f(C[nb][2]) * nm1 + h1.x;
        o1.y = selu_f(C[nb][3]) * nm1 + h1.y;
        *(float2*)(out + (size_t)rg0 * HD + f) = o0;
        *(float2*)(out + (size_t)rg1 * HD + f) = o1;
    }
}

extern "C" void kernel_launch(void* const* d_in, const int* in_sizes, int n_in,
                              void* d_out, int out_size)
{
    const float* h   = (const float*)d_in[0];   // (16,128,256)
    const float* e   = (const float*)d_in[1];   // (16,128,128,30)
    const float* nm  = (const float*)d_in[2];   // (16,128,1)
    const float* em  = (const float*)d_in[3];   // (16,128,128,1)
    const float* Wf  = (const float*)d_in[4];   // (256,30)
    const float* bf  = (const float*)d_in[5];   // (256,)
    const float* Ww  = (const float*)d_in[6];   // (256,512)
    const float* bw  = (const float*)d_in[7];   // (256,)
    float* out = (float*)d_out;                  // (16,128,256)

    cudaFuncSetAttribute(efconv_k2, cudaFuncAttributeMaxDynamicSharedMemorySize, K2_SMEM);

    efconv_k1<<<1024, 256>>>(h, e, em, Wf, bf);
    efconv_k2<<<256, 256, K2_SMEM>>>(h, nm, Ww, bw, out);
}

// round 10
// speedup vs baseline: 2.5344x; 1.0197x over previous
#include <cuda_runtime.h>
#include <cstdint>

#define NBATCH 16
#define NA 128
#define HD 256
#define EF 30

#define SELU_SCALE 1.0507009873554805f
#define SELU_SA    1.7580993408473766f     // scale * alpha
#define LOG2E      1.4426950408889634f
#define SLN2       (1.0507009873554805f * 0.69314718055994531f)  // scale*ln2

// intermediate h1 (16*128*256 fp32 = 2 MB)
__device__ float g_h1[NBATCH * NA * HD];

__device__ __forceinline__ uint32_t f2tf(float x) {
    uint32_t u; asm("cvt.rna.tf32.f32 %0, %1;" : "=r"(u) : "f"(x)); return u;
}
__device__ __forceinline__ float ex2f(float x) {
    float y; asm("ex2.approx.f32 %0, %1;" : "=f"(y) : "f"(x)); return y;
}
// input d2 = d * log2e (log2e folded into weights); output = selu(d)
__device__ __forceinline__ float selu_l2(float d2) {
    float e = ex2f(d2);
    return fmaf(SLN2, fmaxf(d2, 0.f), fminf(fmaf(SELU_SA, e, -SELU_SA), 0.f));
}
__device__ __forceinline__ unsigned long long pack2(float a, float b) {
    unsigned long long v;
    asm("mov.b64 %0, {%1, %2};" : "=l"(v) : "f"(a), "f"(b));
    return v;
}
__device__ __forceinline__ unsigned long long mul2(unsigned long long a,
                                                   unsigned long long b) {
    unsigned long long d;
    asm("mul.rn.f32x2 %0, %1, %2;" : "=l"(d) : "l"(a), "l"(b));
    return d;
}
__device__ __forceinline__ unsigned long long fma2(unsigned long long a,
                                                   unsigned long long b,
                                                   unsigned long long c) {
    unsigned long long d;
    asm("fma.rn.f32x2 %0, %1, %2, %3;" : "=l"(d) : "l"(a), "l"(b), "l"(c));
    return d;
}
__device__ __forceinline__ void unpack2(unsigned long long v, float& a, float& b) {
    asm("mov.b64 {%0, %1}, %2;" : "=f"(a), "=f"(b) : "l"(v));
}
__device__ __forceinline__ void mma_tf32(float c[4],
                                         uint32_t a0, uint32_t a1, uint32_t a2, uint32_t a3,
                                         uint32_t b0, uint32_t b1) {
    asm volatile(
        "mma.sync.aligned.m16n8k8.row.col.f32.tf32.tf32.f32 "
        "{%0,%1,%2,%3}, {%4,%5,%6,%7}, {%8,%9}, {%0,%1,%2,%3};"
        : "+f"(c[0]), "+f"(c[1]), "+f"(c[2]), "+f"(c[3])
        : "r"(a0), "r"(a1), "r"(a2), "r"(a3), "r"(b0), "r"(b1));
}
__device__ __forceinline__ uint32_t smem_u32(const void* p) {
    return (uint32_t)__cvta_generic_to_shared(p);
}
#define CP_ASYNC16(dst_u32, src) \
    asm volatile("cp.async.ca.shared.global [%0], [%1], 16;" \
                 :: "r"(dst_u32), "l"(src))
#define CP_COMMIT() asm volatile("cp.async.commit_group;" ::: "memory")
#define CP_WAIT0()  asm volatile("cp.async.wait_group 0;" ::: "memory")

// =========================================================================
// Kernel 1: CTA = (b, i-tile of 4, f-half of 128). grid = 1024.
// A rows rr = jj*4 + i_l; outputs folded across lanes (l, l^16).
// GEMM weights pre-scaled by log2e. Double-buffered stages:
//   h tile via cp.async (no regs, no cvt — identity row copy);
//   e tile via LDG prefetch + raw-bit STS scatter (tf32 = truncated fp32).
// A in padded fragment order (132-word blocks, 1 LDS.128 -> 4 mma regs).
// =========================================================================
#define EMS 132
#define K1_AFW (16 * 132)
#define K1_HW  (16 * 128)

__global__ __launch_bounds__(256) void efconv_k1(
    const float* __restrict__ hbuf, const float* __restrict__ e,
    const float* __restrict__ edge_mask, const float* __restrict__ Wf,
    const float* __restrict__ bf)
{
    __shared__ uint32_t afb[2][K1_AFW];   // 16.9 KB
    __shared__ float    hqb[2][K1_HW];    // 16 KB
    __shared__ float    em_s[4 * EMS];    //  2.1 KB

    const int tid = threadIdx.x;
    const int w = tid >> 5, l = tid & 31;
    const int r = l >> 2, c = l & 3;
    const int bid = blockIdx.x;
    const int fh = bid & 1, it = (bid >> 1) & 31, b = bid >> 6;
    const int i0 = it * 4;
    const int f0w = fh * 128 + w * 16;
    const int flw = w * 16;

    // ---- h cp.async source/dst lanes (fixed per thread) ----
    const int h_jj0 = tid >> 5, h_fq0 = tid & 31;          // q=0 chunk
    const int h_jj1 = (tid + 256) >> 5, h_fq1 = tid & 31;  // q=1 chunk

    // ---- preload Wf fragments (x log2e, rna) + bias pairs (x log2e) ----
    uint32_t B[4][2][2];
    float2 bfv[2];
    #pragma unroll
    for (int nb = 0; nb < 2; nb++) {
        const int fr = f0w + nb * 8 + r;
        #pragma unroll
        for (int ks = 0; ks < 4; ks++) {
            int k0 = ks * 8 + c, k1 = k0 + 4;
            B[ks][nb][0] = f2tf(Wf[fr * EF + k0] * LOG2E);
            B[ks][nb][1] = (k1 < EF) ? f2tf(Wf[fr * EF + k1] * LOG2E) : 0u;
        }
        float2 bv = *(const float2*)(bf + f0w + nb * 8 + 2 * c);
        bfv[nb] = make_float2(bv.x * LOG2E, bv.y * LOG2E);
    }

    // ---- em[b, i0:i0+4, :] once ----
    #pragma unroll
    for (int q = 0; q < 2; q++) {
        int idx = tid + q * 256;
        int i_l = idx >> 7, j = idx & 127;
        em_s[i_l * EMS + j] = edge_mask[((b * NA) + i0 + i_l) * NA + j];
    }
    // ---- zero k=30,31 fragment slots (both buffers) ----
    if (tid < 64) {
        int rr = tid, t = rr >> 4, rloc = rr & 15;
        int rbit = rloc >> 3, r8 = rloc & 7;
        int base = (t * 4 + 3) * 132 + r8 * 16;
        #pragma unroll
        for (int bu = 0; bu < 2; bu++) {
            afb[bu][base + 2 * 4 + (rbit | 2)] = 0u;
            afb[bu][base + 3 * 4 + (rbit | 2)] = 0u;
        }
    }

    // ---- prologue: stage jt = 0 ----
    {
        CP_ASYNC16(smem_u32(hqb[0] + h_jj0 * 128 + h_fq0 * 4),
                   hbuf + (size_t)(b * NA + h_jj0) * HD + fh * 128 + h_fq0 * 4);
        CP_ASYNC16(smem_u32(hqb[0] + h_jj1 * 128 + h_fq1 * 4),
                   hbuf + (size_t)(b * NA + h_jj1) * HD + fh * 128 + h_fq1 * 4);
        CP_COMMIT();
        #pragma unroll
        for (int q = 0; q < 4; q++) {
            int idx = tid + q * 256;
            if (idx < 960) {
                int i_l = idx / 240, rem = idx - i_l * 240;
                int jj = rem / 15, p = rem - jj * 15;
                float2 v = *(const float2*)(
                    e + ((size_t)((b * NA + i0 + i_l) * NA) + jj) * EF + 2 * p);
                int rr = jj * 4 + i_l;
                int t = rr >> 4, rloc = rr & 15;
                int rbit = rloc >> 3, r8 = rloc & 7;
                int ks = p >> 2, kin = (2 * p) & 7;
                int c0 = kin & 3, chalf = kin >> 2;
                int slot = (t * 4 + ks) * 132 + (r8 * 4 + c0) * 4 + (rbit | (chalf << 1));
                afb[0][slot]     = __float_as_uint(v.x);   // raw bits = tf32 trunc
                afb[0][slot + 4] = __float_as_uint(v.y);
            }
        }
        CP_WAIT0();
    }
    __syncthreads();

    unsigned long long acc2[2] = {};

    #pragma unroll 1
    for (int jt = 0; jt < 8; jt++) {
        const int buf = jt & 1;

        // ---- issue next stage: h via cp.async, e LDG prefetch ----
        float2 va[4];
        if (jt < 7) {
            const int jn = (jt + 1) * 16;
            CP_ASYNC16(smem_u32(hqb[buf ^ 1] + h_jj0 * 128 + h_fq0 * 4),
                       hbuf + (size_t)(b * NA + jn + h_jj0) * HD + fh * 128 + h_fq0 * 4);
            CP_ASYNC16(smem_u32(hqb[buf ^ 1] + h_jj1 * 128 + h_fq1 * 4),
                       hbuf + (size_t)(b * NA + jn + h_jj1) * HD + fh * 128 + h_fq1 * 4);
            CP_COMMIT();
            #pragma unroll
            for (int q = 0; q < 4; q++) {
                int idx = tid + q * 256;
                if (idx < 960) {
                    int i_l = idx / 240, rem = idx - i_l * 240;
                    int jj = rem / 15, p = rem - jj * 15;
                    va[q] = *(const float2*)(
                        e + ((size_t)((b * NA + i0 + i_l) * NA) + jn + jj) * EF + 2 * p);
                }
            }
        }

        const uint32_t* af = afb[buf];
        const float*    hq = hqb[buf];

        // ---- compute stage jt ----
        #pragma unroll
        for (int t = 0; t < 4; t++) {
            const int qa = r >> 2;
            const float em0 = em_s[(r & 3) * EMS + jt * 16 + t * 4 + qa];
            const float em1 = em_s[(r & 3) * EMS + jt * 16 + t * 4 + qa + 2];
            const unsigned long long em0p = pack2(em0, em0);
            const unsigned long long em1p = pack2(em1, em1);
            float C[2][4];
            #pragma unroll
            for (int nb = 0; nb < 2; nb++) {
                C[nb][0] = bfv[nb].x; C[nb][1] = bfv[nb].y;
                C[nb][2] = bfv[nb].x; C[nb][3] = bfv[nb].y;
            }
            #pragma unroll
            for (int ks = 0; ks < 4; ks++) {
                uint4 av = *(const uint4*)(af + (t * 4 + ks) * 132 + l * 4);
                mma_tf32(C[0], av.x, av.y, av.z, av.w, B[ks][0][0], B[ks][0][1]);
                mma_tf32(C[1], av.x, av.y, av.z, av.w, B[ks][1][0], B[ks][1][1]);
            }
            #pragma unroll
            for (int nb = 0; nb < 2; nb++) {
                const int fl = flw + nb * 8 + 2 * c;
                unsigned long long h0 =
                    *(const unsigned long long*)(hq + (t * 4 + qa) * 128 + fl);
                unsigned long long h1 =
                    *(const unsigned long long*)(hq + (t * 4 + qa + 2) * 128 + fl);
                unsigned long long s01 = mul2(pack2(selu_l2(C[nb][0]), selu_l2(C[nb][1])), em0p);
                unsigned long long s23 = mul2(pack2(selu_l2(C[nb][2]), selu_l2(C[nb][3])), em1p);
                acc2[nb] = fma2(s01, h0, acc2[nb]);
                acc2[nb] = fma2(s23, h1, acc2[nb]);
            }
        }

        // ---- STS e frags for stage jt+1, wait cp.async, barrier ----
        if (jt < 7) {
            uint32_t* af1 = afb[buf ^ 1];
            #pragma unroll
            for (int q = 0; q < 4; q++) {
                int idx = tid + q * 256;
                if (idx < 960) {
                    int i_l = idx / 240, rem = idx - i_l * 240;
                    int jj = rem / 15, p = rem - jj * 15;
                    int rr = jj * 4 + i_l;
                    int t = rr >> 4, rloc = rr & 15;
                    int rbit = rloc >> 3, r8 = rloc & 7;
                    int ks = p >> 2, kin = (2 * p) & 7;
                    int c0 = kin & 3, chalf = kin >> 2;
                    int slot = (t * 4 + ks) * 132 + (r8 * 4 + c0) * 4 + (rbit | (chalf << 1));
                    af1[slot]     = __float_as_uint(va[q].x);
                    af1[slot + 4] = __float_as_uint(va[q].y);
                }
            }
            CP_WAIT0();
            __syncthreads();
        }
    }

    // ---- combine lane pairs (l, l^16) and write h1 ----
    #pragma unroll
    for (int nb = 0; nb < 2; nb++) {
        float a0, a1; unpack2(acc2[nb], a0, a1);
        a0 += __shfl_xor_sync(0xffffffffu, a0, 16);
        a1 += __shfl_xor_sync(0xffffffffu, a1, 16);
        if (l < 16) {
            const int f = f0w + nb * 8 + 2 * c;
            *(float2*)(g_h1 + (size_t)(b * NA + i0 + r) * HD + f) = make_float2(a0, a1);
        }
    }
}

// =========================================================================
// Kernel 2: out = selu([h|h1] @ Ww^T + bw) * nm + h
// M=2048, K=512, N=256. Grid 256 = 64 rb x 4 fb; CTA = 32 rows x 64 f.
// LDG-early/STS-late double-buffered K-chunks of 64. Fragment-order smem.
// Ww/bw pre-scaled by log2e (epilogue selu_l2); z staged as raw fp32 bits.
// =========================================================================
#define K2_ZW (16 * 132)
#define K2_WW (8 * 516)
#define K2_SMEM ((2*K2_ZW + 2*K2_WW) * 4)

__global__ __launch_bounds__(256) void efconv_k2(
    const float* __restrict__ hbuf, const float* __restrict__ node_mask,
    const float* __restrict__ Ww, const float* __restrict__ bw,
    float* __restrict__ out)
{
    extern __shared__ uint32_t sm2[];
    uint32_t* zfb[2] = { sm2, sm2 + K2_ZW };
    uint32_t* wfb[2] = { sm2 + 2 * K2_ZW, sm2 + 2 * K2_ZW + K2_WW };

    const int tid = threadIdx.x;
    const int w = tid >> 5, l = tid & 31;
    const int r = l >> 2, c = l & 3;
    const int rb = blockIdx.x >> 2, fb = blockIdx.x & 3;
    const int row0 = rb * 32;
    const int rt = w & 1, fh = w >> 1;

    float C[2][4];
    #pragma unroll
    for (int nb = 0; nb < 2; nb++) {
        float2 bv = *(const float2*)(bw + fb * 64 + fh * 16 + nb * 8 + 2 * c);
        C[nb][0] = bv.x * LOG2E; C[nb][1] = bv.y * LOG2E;
        C[nb][2] = bv.x * LOG2E; C[nb][3] = bv.y * LOG2E;
    }

    // ---- prologue: stage kc = 0 ----
    {
        #pragma unroll
        for (int q = 0; q < 2; q++) {
            int idx = tid + q * 256;
            int rr = idx >> 4, kq = idx & 15;
            float4 v = *(const float4*)(hbuf + (size_t)(row0 + rr) * HD + kq * 4);
            int rt2 = rr >> 4, rloc = rr & 15;
            int rbit = rloc >> 3, r8 = rloc & 7;
            int ks = kq >> 1, chalf = kq & 1;
            uint32_t* d = zfb[0] + (rt2 * 8 + ks) * 132 + r8 * 16 + (rbit | (chalf << 1));
            d[0] = __float_as_uint(v.x); d[4] = __float_as_uint(v.y);
            d[8] = __float_as_uint(v.z); d[12] = __float_as_uint(v.w);
        }
        #pragma unroll
        for (int q = 0; q < 4; q++) {
            int idx = tid + q * 256;
            int ff = idx >> 4, kq = idx & 15;
            float4 v = *(const float4*)(Ww + (size_t)(fb * 64 + ff) * (2 * HD) + kq * 4);
            int ks = kq >> 1, half = kq & 1;
            uint32_t* d = wfb[0] + ks * 516 + ff * 8 + half;
            d[0] = f2tf(v.x * LOG2E); d[2] = f2tf(v.y * LOG2E);
            d[4] = f2tf(v.z * LOG2E); d[6] = f2tf(v.w * LOG2E);
        }
    }
    __syncthreads();

    #pragma unroll 1
    for (int kc = 0; kc < 8; kc++) {
        const int buf = kc & 1;

        // ---- prefetch stage kc+1 (LDG only) ----
        float4 zv[2], wv[4];
        if (kc < 7) {
            const float* zsrc = (kc + 1 < 4) ? hbuf : g_h1;
            const int cb = ((kc + 1) & 3) * 64;
            #pragma unroll
            for (int q = 0; q < 2; q++) {
                int idx = tid + q * 256;
                int rr = idx >> 4, kq = idx & 15;
                zv[q] = *(const float4*)(zsrc + (size_t)(row0 + rr) * HD + cb + kq * 4);
            }
            #pragma unroll
            for (int q = 0; q < 4; q++) {
                int idx = tid + q * 256;
                int ff = idx >> 4, kq = idx & 15;
                wv[q] = *(const float4*)(
                    Ww + (size_t)(fb * 64 + ff) * (2 * HD) + (kc + 1) * 64 + kq * 4);
            }
        }

        // ---- compute stage kc ----
        const uint32_t* zf = zfb[buf];
        const uint32_t* wf = wfb[buf];
        #pragma unroll
        for (int ks = 0; ks < 8; ks++) {
            uint4 av = *(const uint4*)(zf + (rt * 8 + ks) * 132 + l * 4);
            #pragma unroll
            for (int nb = 0; nb < 2; nb++) {
                const int fl = fh * 16 + nb * 8 + r;
                uint2 bb = *(const uint2*)(wf + ks * 516 + fl * 8 + c * 2);
                mma_tf32(C[nb], av.x, av.y, av.z, av.w, bb.x, bb.y);
            }
        }

        // ---- STS stage kc+1 + barrier ----
        if (kc < 7) {
            uint32_t* zf1 = zfb[buf ^ 1];
            uint32_t* wf1 = wfb[buf ^ 1];
            #pragma unroll
            for (int q = 0; q < 2; q++) {
                int idx = tid + q * 256;
                int rr = idx >> 4, kq = idx & 15;
                int rt2 = rr >> 4, rloc = rr & 15;
                int rbit = rloc >> 3, r8 = rloc & 7;
                int ks = kq >> 1, chalf = kq & 1;
                uint32_t* d = zf1 + (rt2 * 8 + ks) * 132 + r8 * 16 + (rbit | (chalf << 1));
                d[0] = __float_as_uint(zv[q].x); d[4] = __float_as_uint(zv[q].y);
                d[8] = __float_as_uint(zv[q].z); d[12] = __float_as_uint(zv[q].w);
            }
            #pragma unroll
            for (int q = 0; q < 4; q++) {
                int idx = tid + q * 256;
                int ff = idx >> 4, kq = idx & 15;
                int ks = kq >> 1, half = kq & 1;
                uint32_t* d = wf1 + ks * 516 + ff * 8 + half;
                d[0] = f2tf(wv[q].x * LOG2E); d[2] = f2tf(wv[q].y * LOG2E);
                d[4] = f2tf(wv[q].z * LOG2E); d[6] = f2tf(wv[q].w * LOG2E);
            }
            __syncthreads();
        }
    }

    // ---- epilogue: selu(D) * nm + h  (C = d*log2e) ----
    const int rg0 = row0 + rt * 16 + r, rg1 = rg0 + 8;
    const float nm0 = node_mask[rg0], nm1 = node_mask[rg1];
    #pragma unroll
    for (int nb = 0; nb < 2; nb++) {
        int f = fb * 64 + fh * 16 + nb * 8 + 2 * c;
        float2 h0 = *(const float2*)(hbuf + (size_t)rg0 * HD + f);
        float2 h1 = *(const float2*)(hbuf + (size_t)rg1 * HD + f);
        float2 o0, o1;
        o0.x = selu_l2(C[nb][0]) * nm0 + h0.x;
        o0.y = selu_l2(C[nb][1]) * nm0 + h0.y;
        o1.x = selu_l2(C[nb][2]) * nm1 + h1.x;
        o1.y = selu_l2(C[nb][3]) * nm1 + h1.y;
        *(float2*)(out + (size_t)rg0 * HD + f) = o0;
        *(float2*)(out + (size_t)rg1 * HD + f) = o1;
    }
}

extern "C" void kernel_launch(void* const* d_in, const int* in_sizes, int n_in,
                              void* d_out, int out_size)
{
    const float* h   = (const float*)d_in[0];   // (16,128,256)
    const float* e   = (const float*)d_in[1];   // (16,128,128,30)
    const float* nm  = (const float*)d_in[2];   // (16,128,1)
    const float* em  = (const float*)d_in[3];   // (16,128,128,1)
    const float* Wf  = (const float*)d_in[4];   // (256,30)
    const float* bf  = (const float*)d_in[5];   // (256,)
    const float* Ww  = (const float*)d_in[6];   // (256,512)
    const float* bw  = (const float*)d_in[7];   // (256,)
    float* out = (float*)d_out;                  // (16,128,256)

    cudaFuncSetAttribute(efconv_k2, cudaFuncAttributeMaxDynamicSharedMemorySize, K2_SMEM);

    efconv_k1<<<1024, 256>>>(h, e, em, Wf, bf);
    efconv_k2<<<256, 256, K2_SMEM>>>(h, nm, Ww, bw, out);
}

// round 12
// speedup vs baseline: 2.6744x; 1.0552x over previous
#include <cuda_runtime.h>
#include <cstdint>

#define NBATCH 16
#define NA 128
#define HD 256
#define EF 30

#define SELU_SCALE 1.0507009873554805f
#define SELU_SA    1.7580993408473766f     // scale * alpha
#define LOG2E      1.4426950408889634f
#define SLN2       (1.0507009873554805f * 0.69314718055994531f)  // scale*ln2
#define SA_H2      0x3F083F08u             // f16x2 {1.7578125, 1.7578125}
#define NSA_H2     0xBF08BF08u             // f16x2 {-1.7578125, -1.7578125}

// intermediate h1 (16*128*256 fp32 = 2 MB)
__device__ float g_h1[NBATCH * NA * HD];

__device__ __forceinline__ uint32_t f2tf(float x) {
    uint32_t u; asm("cvt.rna.tf32.f32 %0, %1;" : "=r"(u) : "f"(x)); return u;
}
__device__ __forceinline__ float ex2f(float x) {
    float y; asm("ex2.approx.f32 %0, %1;" : "=f"(y) : "f"(x)); return y;
}
// scalar selu on d2 = d*log2e (for k2 epilogue)
__device__ __forceinline__ float selu_l2(float d2) {
    float e = ex2f(d2);
    return fmaf(SLN2, fmaxf(d2, 0.f), fminf(fmaf(SELU_SA, e, -SELU_SA), 0.f));
}
__device__ __forceinline__ unsigned long long pack2(float a, float b) {
    unsigned long long v;
    asm("mov.b64 %0, {%1, %2};" : "=l"(v) : "f"(a), "f"(b));
    return v;
}
__device__ __forceinline__ unsigned long long mul2(unsigned long long a,
                                                   unsigned long long b) {
    unsigned long long d;
    asm("mul.rn.f32x2 %0, %1, %2;" : "=l"(d) : "l"(a), "l"(b));
    return d;
}
__device__ __forceinline__ unsigned long long fma2(unsigned long long a,
                                                   unsigned long long b,
                                                   unsigned long long c) {
    unsigned long long d;
    asm("fma.rn.f32x2 %0, %1, %2, %3;" : "=l"(d) : "l"(a), "l"(b), "l"(c));
    return d;
}
__device__ __forceinline__ void unpack2(unsigned long long v, float& a, float& b) {
    asm("mov.b64 {%0, %1}, %2;" : "=f"(a), "=f"(b) : "l"(v));
}
// packed selu pair: inputs (c0, c1) = d*log2e; returns f32x2 {selu(d0), selu(d1)}
// negative branch via ONE ex2.approx.f16x2 (single MUFU slot for 2 elements);
// positive branch fp32 for precision. Overflow/underflow of f16 e saturates
// correctly (inf -> min(inf,0)=0 ; 0 -> -SA).
__device__ __forceinline__ unsigned long long selu2(float c0, float c1) {
    uint32_t h2, e2, f2, n2;
    asm("cvt.rn.f16x2.f32 %0, %1, %2;" : "=r"(h2) : "f"(c1), "f"(c0)); // lo=c0
    asm("ex2.approx.f16x2 %0, %1;" : "=r"(e2) : "r"(h2));
    asm("fma.rn.f16x2 %0, %1, %2, %3;"
        : "=r"(f2) : "r"(e2), "r"(SA_H2), "r"(NSA_H2));
    asm("min.f16x2 %0, %1, %2;" : "=r"(n2) : "r"(f2), "r"(0u));
    float n0, n1;
    asm("{ .reg .b16 lo, hi;\n\t"
        "mov.b32 {lo, hi}, %2;\n\t"
        "cvt.f32.f16 %0, lo;\n\t"
        "cvt.f32.f16 %1, hi; }"
        : "=f"(n0), "=f"(n1) : "r"(n2));
    float s0 = fmaf(SLN2, fmaxf(c0, 0.f), n0);
    float s1 = fmaf(SLN2, fmaxf(c1, 0.f), n1);
    return pack2(s0, s1);
}
__device__ __forceinline__ void mma_tf32(float c[4],
                                         uint32_t a0, uint32_t a1, uint32_t a2, uint32_t a3,
                                         uint32_t b0, uint32_t b1) {
    asm volatile(
        "mma.sync.aligned.m16n8k8.row.col.f32.tf32.tf32.f32 "
        "{%0,%1,%2,%3}, {%4,%5,%6,%7}, {%8,%9}, {%0,%1,%2,%3};"
        : "+f"(c[0]), "+f"(c[1]), "+f"(c[2]), "+f"(c[3])
        : "r"(a0), "r"(a1), "r"(a2), "r"(a3), "r"(b0), "r"(b1));
}
__device__ __forceinline__ uint32_t smem_u32(const void* p) {
    return (uint32_t)__cvta_generic_to_shared(p);
}
#define CP_ASYNC16(dst_u32, src) \
    asm volatile("cp.async.ca.shared.global [%0], [%1], 16;" \
                 :: "r"(dst_u32), "l"(src))
#define CP_COMMIT() asm volatile("cp.async.commit_group;" ::: "memory")
#define CP_WAIT0()  asm volatile("cp.async.wait_group 0;" ::: "memory")

// =========================================================================
// Kernel 1: CTA = (b, i-tile of 4, f-half of 128). grid = 1024.
// A rows rr = jj*4 + i_l; outputs folded across lanes (l, l^16).
// Wf pre-scaled by log2e (rna); e staged with rna tf32 (unbiased).
// Double-buffered: h via cp.async, e via LDG-early/STS-late.
// A in padded fragment order (132-word blocks). Packed f16x2 selu epilogue.
// =========================================================================
#define EMS 132
#define K1_AFW (16 * 132)
#define K1_HW  (16 * 128)

__global__ __launch_bounds__(256) void efconv_k1(
    const float* __restrict__ hbuf, const float* __restrict__ e,
    const float* __restrict__ edge_mask, const float* __restrict__ Wf,
    const float* __restrict__ bf)
{
    __shared__ uint32_t afb[2][K1_AFW];
    __shared__ float    hqb[2][K1_HW];
    __shared__ float    em_s[4 * EMS];

    const int tid = threadIdx.x;
    const int w = tid >> 5, l = tid & 31;
    const int r = l >> 2, c = l & 3;
    const int bid = blockIdx.x;
    const int fh = bid & 1, it = (bid >> 1) & 31, b = bid >> 6;
    const int i0 = it * 4;
    const int f0w = fh * 128 + w * 16;
    const int flw = w * 16;

    const int h_jj0 = tid >> 5, h_fq0 = tid & 31;
    const int h_jj1 = (tid + 256) >> 5, h_fq1 = tid & 31;

    // ---- preload Wf fragments (x log2e, rna) + bias pairs (x log2e) ----
    uint32_t B[4][2][2];
    float2 bfv[2];
    #pragma unroll
    for (int nb = 0; nb < 2; nb++) {
        const int fr = f0w + nb * 8 + r;
        #pragma unroll
        for (int ks = 0; ks < 4; ks++) {
            int k0 = ks * 8 + c, k1 = k0 + 4;
            B[ks][nb][0] = f2tf(Wf[fr * EF + k0] * LOG2E);
            B[ks][nb][1] = (k1 < EF) ? f2tf(Wf[fr * EF + k1] * LOG2E) : 0u;
        }
        float2 bv = *(const float2*)(bf + f0w + nb * 8 + 2 * c);
        bfv[nb] = make_float2(bv.x * LOG2E, bv.y * LOG2E);
    }

    // ---- em[b, i0:i0+4, :] once ----
    #pragma unroll
    for (int q = 0; q < 2; q++) {
        int idx = tid + q * 256;
        int i_l = idx >> 7, j = idx & 127;
        em_s[i_l * EMS + j] = edge_mask[((b * NA) + i0 + i_l) * NA + j];
    }
    // ---- zero k=30,31 fragment slots (both buffers) ----
    if (tid < 64) {
        int rr = tid, t = rr >> 4, rloc = rr & 15;
        int rbit = rloc >> 3, r8 = rloc & 7;
        int base = (t * 4 + 3) * 132 + r8 * 16;
        #pragma unroll
        for (int bu = 0; bu < 2; bu++) {
            afb[bu][base + 2 * 4 + (rbit | 2)] = 0u;
            afb[bu][base + 3 * 4 + (rbit | 2)] = 0u;
        }
    }

    // ---- prologue: stage jt = 0 ----
    {
        CP_ASYNC16(smem_u32(hqb[0] + h_jj0 * 128 + h_fq0 * 4),
                   hbuf + (size_t)(b * NA + h_jj0) * HD + fh * 128 + h_fq0 * 4);
        CP_ASYNC16(smem_u32(hqb[0] + h_jj1 * 128 + h_fq1 * 4),
                   hbuf + (size_t)(b * NA + h_jj1) * HD + fh * 128 + h_fq1 * 4);
        CP_COMMIT();
        #pragma unroll
        for (int q = 0; q < 4; q++) {
            int idx = tid + q * 256;
            if (idx < 960) {
                int i_l = idx / 240, rem = idx - i_l * 240;
                int jj = rem / 15, p = rem - jj * 15;
                float2 v = *(const float2*)(
                    e + ((size_t)((b * NA + i0 + i_l) * NA) + jj) * EF + 2 * p);
                int rr = jj * 4 + i_l;
                int t = rr >> 4, rloc = rr & 15;
                int rbit = rloc >> 3, r8 = rloc & 7;
                int ks = p >> 2, kin = (2 * p) & 7;
                int c0 = kin & 3, chalf = kin >> 2;
                int slot = (t * 4 + ks) * 132 + (r8 * 4 + c0) * 4 + (rbit | (chalf << 1));
                afb[0][slot]     = f2tf(v.x);
                afb[0][slot + 4] = f2tf(v.y);
            }
        }
        CP_WAIT0();
    }
    __syncthreads();

    unsigned long long acc2[2] = {};

    #pragma unroll 1
    for (int jt = 0; jt < 8; jt++) {
        const int buf = jt & 1;

        // ---- issue next stage: h via cp.async, e LDG prefetch ----
        float2 va[4];
        if (jt < 7) {
            const int jn = (jt + 1) * 16;
            CP_ASYNC16(smem_u32(hqb[buf ^ 1] + h_jj0 * 128 + h_fq0 * 4),
                       hbuf + (size_t)(b * NA + jn + h_jj0) * HD + fh * 128 + h_fq0 * 4);
            CP_ASYNC16(smem_u32(hqb[buf ^ 1] + h_jj1 * 128 + h_fq1 * 4),
                       hbuf + (size_t)(b * NA + jn + h_jj1) * HD + fh * 128 + h_fq1 * 4);
            CP_COMMIT();
            #pragma unroll
            for (int q = 0; q < 4; q++) {
                int idx = tid + q * 256;
                if (idx < 960) {
                    int i_l = idx / 240, rem = idx - i_l * 240;
                    int jj = rem / 15, p = rem - jj * 15;
                    va[q] = *(const float2*)(
                        e + ((size_t)((b * NA + i0 + i_l) * NA) + jn + jj) * EF + 2 * p);
                }
            }
        }

        const uint32_t* af = afb[buf];
        const float*    hq = hqb[buf];

        // ---- compute stage jt ----
        #pragma unroll
        for (int t = 0; t < 4; t++) {
            const int qa = r >> 2;
            const float em0 = em_s[(r & 3) * EMS + jt * 16 + t * 4 + qa];
            const float em1 = em_s[(r & 3) * EMS + jt * 16 + t * 4 + qa + 2];
            const unsigned long long em0p = pack2(em0, em0);
            const unsigned long long em1p = pack2(em1, em1);
            float C[2][4];
            #pragma unroll
            for (int nb = 0; nb < 2; nb++) {
                C[nb][0] = bfv[nb].x; C[nb][1] = bfv[nb].y;
                C[nb][2] = bfv[nb].x; C[nb][3] = bfv[nb].y;
            }
            #pragma unroll
            for (int ks = 0; ks < 4; ks++) {
                uint4 av = *(const uint4*)(af + (t * 4 + ks) * 132 + l * 4);
                mma_tf32(C[0], av.x, av.y, av.z, av.w, B[ks][0][0], B[ks][0][1]);
                mma_tf32(C[1], av.x, av.y, av.z, av.w, B[ks][1][0], B[ks][1][1]);
            }
            #pragma unroll
            for (int nb = 0; nb < 2; nb++) {
                const int fl = flw + nb * 8 + 2 * c;
                unsigned long long h0 =
                    *(const unsigned long long*)(hq + (t * 4 + qa) * 128 + fl);
                unsigned long long h1 =
                    *(const unsigned long long*)(hq + (t * 4 + qa + 2) * 128 + fl);
                unsigned long long s01 = mul2(selu2(C[nb][0], C[nb][1]), em0p);
                unsigned long long s23 = mul2(selu2(C[nb][2], C[nb][3]), em1p);
                acc2[nb] = fma2(s01, h0, acc2[nb]);
                acc2[nb] = fma2(s23, h1, acc2[nb]);
            }
        }

        // ---- STS e frags for stage jt+1, wait cp.async, barrier ----
        if (jt < 7) {
            uint32_t* af1 = afb[buf ^ 1];
            #pragma unroll
            for (int q = 0; q < 4; q++) {
                int idx = tid + q * 256;
                if (idx < 960) {
                    int i_l = idx / 240, rem = idx - i_l * 240;
                    int jj = rem / 15, p = rem - jj * 15;
                    int rr = jj * 4 + i_l;
                    int t = rr >> 4, rloc = rr & 15;
                    int rbit = rloc >> 3, r8 = rloc & 7;
                    int ks = p >> 2, kin = (2 * p) & 7;
                    int c0 = kin & 3, chalf = kin >> 2;
                    int slot = (t * 4 + ks) * 132 + (r8 * 4 + c0) * 4 + (rbit | (chalf << 1));
                    af1[slot]     = f2tf(va[q].x);
                    af1[slot + 4] = f2tf(va[q].y);
                }
            }
            CP_WAIT0();
            __syncthreads();
        }
    }

    // ---- combine lane pairs (l, l^16) and write h1 ----
    #pragma unroll
    for (int nb = 0; nb < 2; nb++) {
        float a0, a1; unpack2(acc2[nb], a0, a1);
        a0 += __shfl_xor_sync(0xffffffffu, a0, 16);
        a1 += __shfl_xor_sync(0xffffffffu, a1, 16);
        if (l < 16) {
            const int f = f0w + nb * 8 + 2 * c;
            *(float2*)(g_h1 + (size_t)(b * NA + i0 + r) * HD + f) = make_float2(a0, a1);
        }
    }
}

// =========================================================================
// Kernel 2: out = selu([h|h1] @ Ww^T + bw) * nm + h
// M=2048, K=512, N=256. Grid 256 = 64 rb x 4 fb; CTA = 32 rows x 64 f.
// LDG-early/STS-late double-buffered K-chunks of 64. Fragment-order smem.
// Ww/bw pre-scaled by log2e; z staged with rna tf32 (unbiased).
// =========================================================================
#define K2_ZW (16 * 132)
#define K2_WW (8 * 516)
#define K2_SMEM ((2*K2_ZW + 2*K2_WW) * 4)

__global__ __launch_bounds__(256) void efconv_k2(
    const float* __restrict__ hbuf, const float* __restrict__ node_mask,
    const float* __restrict__ Ww, const float* __restrict__ bw,
    float* __restrict__ out)
{
    extern __shared__ uint32_t sm2[];
    uint32_t* zfb[2] = { sm2, sm2 + K2_ZW };
    uint32_t* wfb[2] = { sm2 + 2 * K2_ZW, sm2 + 2 * K2_ZW + K2_WW };

    const int tid = threadIdx.x;
    const int w = tid >> 5, l = tid & 31;
    const int r = l >> 2, c = l & 3;
    const int rb = blockIdx.x >> 2, fb = blockIdx.x & 3;
    const int row0 = rb * 32;
    const int rt = w & 1, fh = w >> 1;

    float C[2][4];
    #pragma unroll
    for (int nb = 0; nb < 2; nb++) {
        float2 bv = *(const float2*)(bw + fb * 64 + fh * 16 + nb * 8 + 2 * c);
        C[nb][0] = bv.x * LOG2E; C[nb][1] = bv.y * LOG2E;
        C[nb][2] = bv.x * LOG2E; C[nb][3] = bv.y * LOG2E;
    }

    // ---- prologue: stage kc = 0 ----
    {
        #pragma unroll
        for (int q = 0; q < 2; q++) {
            int idx = tid + q * 256;
            int rr = idx >> 4, kq = idx & 15;
            float4 v = *(const float4*)(hbuf + (size_t)(row0 + rr) * HD + kq * 4);
            int rt2 = rr >> 4, rloc = rr & 15;
            int rbit = rloc >> 3, r8 = rloc & 7;
            int ks = kq >> 1, chalf = kq & 1;
            uint32_t* d = zfb[0] + (rt2 * 8 + ks) * 132 + r8 * 16 + (rbit | (chalf << 1));
            d[0] = f2tf(v.x); d[4] = f2tf(v.y);
            d[8] = f2tf(v.z); d[12] = f2tf(v.w);
        }
        #pragma unroll
        for (int q = 0; q < 4; q++) {
            int idx = tid + q * 256;
            int ff = idx >> 4, kq = idx & 15;
            float4 v = *(const float4*)(Ww + (size_t)(fb * 64 + ff) * (2 * HD) + kq * 4);
            int ks = kq >> 1, half = kq & 1;
            uint32_t* d = wfb[0] + ks * 516 + ff * 8 + half;
            d[0] = f2tf(v.x * LOG2E); d[2] = f2tf(v.y * LOG2E);
            d[4] = f2tf(v.z * LOG2E); d[6] = f2tf(v.w * LOG2E);
        }
    }
    __syncthreads();

    #pragma unroll 1
    for (int kc = 0; kc < 8; kc++) {
        const int buf = kc & 1;

        // ---- prefetch stage kc+1 (LDG only) ----
        float4 zv[2], wv[4];
        if (kc < 7) {
            const float* zsrc = (kc + 1 < 4) ? hbuf : g_h1;
            const int cb = ((kc + 1) & 3) * 64;
            #pragma unroll
            for (int q = 0; q < 2; q++) {
                int idx = tid + q * 256;
                int rr = idx >> 4, kq = idx & 15;
                zv[q] = *(const float4*)(zsrc + (size_t)(row0 + rr) * HD + cb + kq * 4);
            }
            #pragma unroll
            for (int q = 0; q < 4; q++) {
                int idx = tid + q * 256;
                int ff = idx >> 4, kq = idx & 15;
                wv[q] = *(const float4*)(
                    Ww + (size_t)(fb * 64 + ff) * (2 * HD) + (kc + 1) * 64 + kq * 4);
            }
        }

        // ---- compute stage kc ----
        const uint32_t* zf = zfb[buf];
        const uint32_t* wf = wfb[buf];
        #pragma unroll
        for (int ks = 0; ks < 8; ks++) {
            uint4 av = *(const uint4*)(zf + (rt * 8 + ks) * 132 + l * 4);
            #pragma unroll
            for (int nb = 0; nb < 2; nb++) {
                const int fl = fh * 16 + nb * 8 + r;
                uint2 bb = *(const uint2*)(wf + ks * 516 + fl * 8 + c * 2);
                mma_tf32(C[nb], av.x, av.y, av.z, av.w, bb.x, bb.y);
            }
        }

        // ---- STS stage kc+1 + barrier ----
        if (kc < 7) {
            uint32_t* zf1 = zfb[buf ^ 1];
            uint32_t* wf1 = wfb[buf ^ 1];
            #pragma unroll
            for (int q = 0; q < 2; q++) {
                int idx = tid + q * 256;
                int rr = idx >> 4, kq = idx & 15;
                int rt2 = rr >> 4, rloc = rr & 15;
                int rbit = rloc >> 3, r8 = rloc & 7;
                int ks = kq >> 1, chalf = kq & 1;
                uint32_t* d = zf1 + (rt2 * 8 + ks) * 132 + r8 * 16 + (rbit | (chalf << 1));
                d[0] = f2tf(zv[q].x); d[4] = f2tf(zv[q].y);
                d[8] = f2tf(zv[q].z); d[12] = f2tf(zv[q].w);
            }
            #pragma unroll
            for (int q = 0; q < 4; q++) {
                int idx = tid + q * 256;
                int ff = idx >> 4, kq = idx & 15;
                int ks = kq >> 1, half = kq & 1;
                uint32_t* d = wf1 + ks * 516 + ff * 8 + half;
                d[0] = f2tf(wv[q].x * LOG2E); d[2] = f2tf(wv[q].y * LOG2E);
                d[4] = f2tf(wv[q].z * LOG2E); d[6] = f2tf(wv[q].w * LOG2E);
            }
            __syncthreads();
        }
    }

    // ---- epilogue: selu(D) * nm + h  (C = d*log2e) ----
    const int rg0 = row0 + rt * 16 + r, rg1 = rg0 + 8;
    const float nm0 = node_mask[rg0], nm1 = node_mask[rg1];
    #pragma unroll
    for (int nb = 0; nb < 2; nb++) {
        int f = fb * 64 + fh * 16 + nb * 8 + 2 * c;
        float2 h0 = *(const float2*)(hbuf + (size_t)rg0 * HD + f);
        float2 h1 = *(const float2*)(hbuf + (size_t)rg1 * HD + f);
        float2 o0, o1;
        o0.x = selu_l2(C[nb][0]) * nm0 + h0.x;
        o0.y = selu_l2(C[nb][1]) * nm0 + h0.y;
        o1.x = selu_l2(C[nb][2]) * nm1 + h1.x;
        o1.y = selu_l2(C[nb][3]) * nm1 + h1.y;
        *(float2*)(out + (size_t)rg0 * HD + f) = o0;
        *(float2*)(out + (size_t)rg1 * HD + f) = o1;
    }
}

extern "C" void kernel_launch(void* const* d_in, const int* in_sizes, int n_in,
                              void* d_out, int out_size)
{
    const float* h   = (const float*)d_in[0];   // (16,128,256)
    const float* e   = (const float*)d_in[1];   // (16,128,128,30)
    const float* nm  = (const float*)d_in[2];   // (16,128,1)
    const float* em  = (const float*)d_in[3];   // (16,128,128,1)
    const float* Wf  = (const float*)d_in[4];   // (256,30)
    const float* bf  = (const float*)d_in[5];   // (256,)
    const float* Ww  = (const float*)d_in[6];   // (256,512)
    const float* bw  = (const float*)d_in[7];   // (256,)
    float* out = (float*)d_out;                  // (16,128,256)

    cudaFuncSetAttribute(efconv_k2, cudaFuncAttributeMaxDynamicSharedMemorySize, K2_SMEM);

    efconv_k1<<<1024, 256>>>(h, e, em, Wf, bf);
    efconv_k2<<<256, 256, K2_SMEM>>>(h, nm, Ww, bw, out);
}